// round 3
// baseline (speedup 1.0000x reference)
#include <cuda_runtime.h>
#include <math.h>

#define Nn 50000
#define Ee 200000
#define Hd 128
#define Cc 4
#define Gg 64
#define EDd 16
#define NROWS (Cc*Nn)   // 200000

// ---------------- scratch (device globals; no allocation allowed) ----------------
__device__ __align__(128) float g_ee[Ee*Hd];        // bond-encoded edge features (shared across layers)
__device__ __align__(128) float g_bufA[NROWS*Hd];
__device__ __align__(128) float g_bufB[NROWS*Hd];
__device__ int g_deg[Nn];
__device__ int g_offs[Nn+1];
__device__ int g_cnt[Nn];
__device__ int g_csr[Ee];
__device__ int g_gstart[Gg+1];

__device__ __forceinline__ float gelu_f(float v){
    return 0.5f*v*(1.0f+erff(v*0.7071067811865475f));
}

// ---------------- zero counters ----------------
__global__ void k_zero_counts(){
    int i = blockIdx.x*256 + threadIdx.x;
    if (i < Nn){ g_deg[i]=0; g_cnt[i]=0; }
}

// ---------------- bond encoder: ee[e][h] = edge_attr[e] @ W_be + b_be ----------------
__global__ void k_bond(const float* __restrict__ ea, const float* __restrict__ Wbe,
                       const float* __restrict__ bbe){
    __shared__ float sW[EDd*Hd];
    __shared__ float sattr[16*EDd];
    int tid = threadIdx.x;  // 128
    for (int i=tid;i<EDd*Hd;i+=128) sW[i]=Wbe[i];
    float bias = bbe[tid];
    int e0 = blockIdx.x*16;
    for (int i=tid;i<16*EDd;i+=128){
        int ei = e0 + (i>>4);
        sattr[i] = (ei<Ee) ? ea[ei*EDd + (i&15)] : 0.f;
    }
    __syncthreads();
    #pragma unroll 1
    for (int j=0;j<16;j++){
        int e = e0+j;
        if (e>=Ee) break;
        float acc = bias;
        #pragma unroll
        for (int d=0;d<EDd;d++) acc += sattr[j*EDd+d]*sW[d*Hd+tid];
        g_ee[e*Hd+tid] = acc;
    }
}

// ---------------- CSR build on dst ----------------
__global__ void k_hist(const int* __restrict__ dst){
    int e = blockIdx.x*256 + threadIdx.x;
    if (e < Ee) atomicAdd(&g_deg[dst[e]], 1);
}

__global__ void k_scan(){
    __shared__ int s[1024];
    __shared__ int carry;
    int tid = threadIdx.x;
    if (tid==0) carry = 0;
    __syncthreads();
    for (int base=0; base<Nn; base+=1024){
        int i = base+tid;
        int v = (i<Nn) ? g_deg[i] : 0;
        s[tid] = v; __syncthreads();
        for (int off=1; off<1024; off<<=1){
            int t = (tid>=off) ? s[tid-off] : 0;
            __syncthreads();
            s[tid] += t;
            __syncthreads();
        }
        if (i<Nn) g_offs[i] = carry + s[tid] - v;
        int tot = s[1023];
        __syncthreads();
        if (tid==0) carry += tot;
        __syncthreads();
    }
    if (tid==0) g_offs[Nn] = carry;
}

__global__ void k_fill(const int* __restrict__ dst){
    int e = blockIdx.x*256 + threadIdx.x;
    if (e < Ee){
        int d = dst[e];
        int p = atomicAdd(&g_cnt[d], 1);
        g_csr[g_offs[d]+p] = e;
    }
}

// ---------------- graph boundaries (batch is sorted) ----------------
__global__ void k_gstart(const int* __restrict__ batch){
    int g = threadIdx.x;
    if (g > Gg) return;
    int lo = 0, hi = Nn;
    while (lo < hi){
        int mid = (lo+hi) >> 1;
        if (batch[mid] < g) lo = mid+1; else hi = mid;
    }
    g_gstart[g] = lo;
}

// ---------------- aggregation: h = (1+eps)*x + scatter_sum(gelu(x[src]+ee)*emask) ----------------
// one block (128 threads = h-dim) per node; all 4 centroids handled in-register (ee reused 4x)
__global__ void k_agg(const float* __restrict__ xin, const float* __restrict__ em,
                      const int* __restrict__ src, const float* __restrict__ epsp,
                      int l, float* __restrict__ hout){
    int h = threadIdx.x;
    int n = blockIdx.x;
    float ep = 1.0f + epsp[l];
    int beg = g_offs[n], end = g_offs[n+1];
    float a0 = ep * xin[(0*Nn+n)*Hd+h];
    float a1 = ep * xin[(1*Nn+n)*Hd+h];
    float a2 = ep * xin[(2*Nn+n)*Hd+h];
    float a3 = ep * xin[(3*Nn+n)*Hd+h];
    for (int k=beg; k<end; k++){
        int e = g_csr[k];
        int s = src[e];
        float eeh = g_ee[e*Hd+h];
        float m0 = em[0*Ee+e], m1 = em[1*Ee+e], m2 = em[2*Ee+e], m3 = em[3*Ee+e];
        a0 += gelu_f(xin[(0*Nn+s)*Hd+h] + eeh) * m0;
        a1 += gelu_f(xin[(1*Nn+s)*Hd+h] + eeh) * m1;
        a2 += gelu_f(xin[(2*Nn+s)*Hd+h] + eeh) * m2;
        a3 += gelu_f(xin[(3*Nn+s)*Hd+h] + eeh) * m3;
    }
    hout[(0*Nn+n)*Hd+h] = a0;
    hout[(1*Nn+n)*Hd+h] = a1;
    hout[(2*Nn+n)*Hd+h] = a2;
    hout[(3*Nn+n)*Hd+h] = a3;
}

// ---------------- fused MLP: out = [gelu]( gelu(in@Wa+ba) @ Wb + bb ) ----------------
// 512 threads, 128-row tile, full K=128, both weights resident in smem.
#define SA_LD 132
#define SMEM_MLP ((16384 + 16384 + 128*SA_LD) * 4)

__global__ void __launch_bounds__(512, 1)
k_mlp(const float* __restrict__ in, float* __restrict__ out,
      const float* __restrict__ Wa, const float* __restrict__ ba,
      const float* __restrict__ Wb, const float* __restrict__ bb,
      int rows, int outer_gelu){
    extern __shared__ float smem[];
    float* sWa = smem;              // [128][128]
    float* sWb = smem + 16384;      // [128][128]
    float* sA  = smem + 32768;      // [128][SA_LD]
    const int tid = threadIdx.x;

    {   // weights
        const float4* Wa4 = (const float4*)Wa;
        const float4* Wb4 = (const float4*)Wb;
        float4* sWa4 = (float4*)sWa;
        float4* sWb4 = (float4*)sWb;
        #pragma unroll
        for (int i=tid; i<4096; i+=512){ sWa4[i]=Wa4[i]; sWb4[i]=Wb4[i]; }
    }
    const int base = blockIdx.x*128;
    // A tile (row-major, padded)
    #pragma unroll
    for (int i=tid; i<128*32; i+=512){
        int m = i>>5, kq = i&31;
        float4 v = make_float4(0.f,0.f,0.f,0.f);
        if (base+m < rows) v = *(const float4*)&in[(base+m)*Hd + kq*4];
        *(float4*)&sA[m*SA_LD + kq*4] = v;
    }
    __syncthreads();

    const int n4 = (tid & 31)*4;
    const int m8 = (tid >> 5)*8;
    float acc[8][4];

    // ---- GEMM1 + gelu ----
    {
        float4 bv = *(const float4*)&ba[n4];
        #pragma unroll
        for (int mi=0;mi<8;mi++){ acc[mi][0]=bv.x; acc[mi][1]=bv.y; acc[mi][2]=bv.z; acc[mi][3]=bv.w; }
        #pragma unroll 4
        for (int k=0;k<128;k+=4){
            float4 w0 = *(float4*)&sWa[(k+0)*Hd + n4];
            float4 w1 = *(float4*)&sWa[(k+1)*Hd + n4];
            float4 w2 = *(float4*)&sWa[(k+2)*Hd + n4];
            float4 w3 = *(float4*)&sWa[(k+3)*Hd + n4];
            #pragma unroll
            for (int mi=0;mi<8;mi++){
                float4 a = *(float4*)&sA[(m8+mi)*SA_LD + k];
                acc[mi][0] += a.x*w0.x + a.y*w1.x + a.z*w2.x + a.w*w3.x;
                acc[mi][1] += a.x*w0.y + a.y*w1.y + a.z*w2.y + a.w*w3.y;
                acc[mi][2] += a.x*w0.z + a.y*w1.z + a.z*w2.z + a.w*w3.z;
                acc[mi][3] += a.x*w0.w + a.y*w1.w + a.z*w2.w + a.w*w3.w;
            }
        }
        #pragma unroll
        for (int mi=0;mi<8;mi++)
            #pragma unroll
            for (int j=0;j<4;j++) acc[mi][j] = gelu_f(acc[mi][j]);
    }
    __syncthreads();   // all reads of sA done
    #pragma unroll
    for (int mi=0;mi<8;mi++)
        *(float4*)&sA[(m8+mi)*SA_LD + n4] = make_float4(acc[mi][0],acc[mi][1],acc[mi][2],acc[mi][3]);
    __syncthreads();

    // ---- GEMM2 + optional gelu ----
    {
        float4 bv = *(const float4*)&bb[n4];
        #pragma unroll
        for (int mi=0;mi<8;mi++){ acc[mi][0]=bv.x; acc[mi][1]=bv.y; acc[mi][2]=bv.z; acc[mi][3]=bv.w; }
        #pragma unroll 4
        for (int k=0;k<128;k+=4){
            float4 w0 = *(float4*)&sWb[(k+0)*Hd + n4];
            float4 w1 = *(float4*)&sWb[(k+1)*Hd + n4];
            float4 w2 = *(float4*)&sWb[(k+2)*Hd + n4];
            float4 w3 = *(float4*)&sWb[(k+3)*Hd + n4];
            #pragma unroll
            for (int mi=0;mi<8;mi++){
                float4 a = *(float4*)&sA[(m8+mi)*SA_LD + k];
                acc[mi][0] += a.x*w0.x + a.y*w1.x + a.z*w2.x + a.w*w3.x;
                acc[mi][1] += a.x*w0.y + a.y*w1.y + a.z*w2.y + a.w*w3.y;
                acc[mi][2] += a.x*w0.z + a.y*w1.z + a.z*w2.z + a.w*w3.z;
                acc[mi][3] += a.x*w0.w + a.y*w1.w + a.z*w2.w + a.w*w3.w;
            }
        }
        #pragma unroll
        for (int mi=0;mi<8;mi++){
            if (base+m8+mi < rows){
                float4 o;
                if (outer_gelu){
                    o = make_float4(gelu_f(acc[mi][0]),gelu_f(acc[mi][1]),gelu_f(acc[mi][2]),gelu_f(acc[mi][3]));
                } else {
                    o = make_float4(acc[mi][0],acc[mi][1],acc[mi][2],acc[mi][3]);
                }
                *(float4*)&out[(base+m8+mi)*Hd + n4] = o;
            }
        }
    }
}

// ---------------- masked mean pool per (graph, centroid) ----------------
__global__ void k_pool(const float* __restrict__ y, const float* __restrict__ nm,
                       float* __restrict__ out){
    int f = threadIdx.x;          // 128
    int g = blockIdx.x, c = blockIdx.y;
    int beg = g_gstart[g], end = g_gstart[g+1];
    float num = 0.f, den = 0.f;
    for (int n=beg; n<end; n++){
        float m = nm[c*Nn+n];
        num += y[(c*Nn+n)*Hd+f]*m;
        den += m;
    }
    out[(g*Cc+c)*Hd+f] = num / (den + 1e-7f);
}

// ---------------- launch ----------------
extern "C" void kernel_launch(void* const* d_in, const int* in_sizes, int n_in,
                              void* d_out, int out_size){
    const float* x    = (const float*)d_in[0];
    const int*  batch = (const int*)d_in[1];
    const int*  eidx  = (const int*)d_in[2];
    const float* ea   = (const float*)d_in[3];
    const float* nm   = (const float*)d_in[4];
    const float* em   = (const float*)d_in[5];
    const float* Wbe  = (const float*)d_in[6];
    const float* bbe  = (const float*)d_in[7];
    const float* eps  = (const float*)d_in[8];
    const float* W1   = (const float*)d_in[9];
    const float* b1   = (const float*)d_in[10];
    const float* W2   = (const float*)d_in[11];
    const float* b2   = (const float*)d_in[12];
    const float* Wm1  = (const float*)d_in[13];
    const float* bm1  = (const float*)d_in[14];
    const float* Wm2  = (const float*)d_in[15];
    const float* bm2  = (const float*)d_in[16];
    float* out = (float*)d_out;

    const int* src = eidx;
    const int* dst = eidx + Ee;

    float *bufA, *bufB;
    cudaGetSymbolAddress((void**)&bufA, g_bufA);
    cudaGetSymbolAddress((void**)&bufB, g_bufB);
    cudaFuncSetAttribute(k_mlp, cudaFuncAttributeMaxDynamicSharedMemorySize, SMEM_MLP);

    const int mlp_grid = (NROWS + 127)/128;

    k_zero_counts<<<(Nn+255)/256, 256>>>();
    k_bond<<<(Ee+15)/16, 128>>>(ea, Wbe, bbe);
    k_hist<<<(Ee+255)/256, 256>>>(dst);
    k_scan<<<1, 1024>>>();
    k_fill<<<(Ee+255)/256, 256>>>(dst);
    k_gstart<<<1, 128>>>(batch);

    // layer 0
    k_agg<<<Nn, 128>>>(x, em, src, eps, 0, bufA);
    k_mlp<<<mlp_grid, 512, SMEM_MLP>>>(bufA, bufB, W1, b1, W2, b2, NROWS, 1);
    // layer 1
    k_agg<<<Nn, 128>>>(bufB, em, src, eps, 1, bufA);
    k_mlp<<<mlp_grid, 512, SMEM_MLP>>>(bufA, bufB, W1 + Hd*Hd, b1 + Hd, W2 + Hd*Hd, b2 + Hd, NROWS, 1);
    // final MLP (no outer gelu)
    k_mlp<<<mlp_grid, 512, SMEM_MLP>>>(bufB, bufA, Wm1, bm1, Wm2, bm2, NROWS, 0);
    // pool
    k_pool<<<dim3(Gg, Cc), 128>>>(bufA, nm, out);
}

// round 4
// speedup vs baseline: 1.1466x; 1.1466x over previous
#include <cuda_runtime.h>
#include <math.h>

#define Nn 50000
#define Ee 200000
#define Hd 128
#define Cc 4
#define Gg 64
#define EDd 16
#define NROWS (Cc*Nn)   // 200000
#define NBLK_SCAN ((Nn + 1023)/1024)   // 49

// ---------------- scratch (device globals; no allocation allowed) ----------------
__device__ __align__(128) float g_ee[Ee*Hd];
__device__ __align__(128) float g_bufA[NROWS*Hd];
__device__ __align__(128) float g_bufB[NROWS*Hd];
__device__ int g_deg[Nn];
__device__ int g_offs[Nn+1];
__device__ int g_cnt[Nn];
__device__ int g_csr[Ee];
__device__ int g_gstart[Gg+1];
__device__ int g_bsum[NBLK_SCAN];
__device__ int g_boff[NBLK_SCAN+1];

__device__ __forceinline__ float gelu_f(float v){
    return 0.5f*v*(1.0f+erff(v*0.7071067811865475f));
}

// ---- packed f32x2 helpers (sm_100+ PTX) ----
typedef unsigned long long ull;
__device__ __forceinline__ ull pk(float a, float b){
    ull r; asm("mov.b64 %0, {%1,%2};" : "=l"(r) : "f"(a), "f"(b)); return r;
}
__device__ __forceinline__ ull pkb(float a){
    ull r; asm("mov.b64 %0, {%1,%1};" : "=l"(r) : "f"(a)); return r;
}
__device__ __forceinline__ void fma2(ull &d, ull a, ull b){
    asm("fma.rn.f32x2 %0, %1, %2, %0;" : "+l"(d) : "l"(a), "l"(b));
}
__device__ __forceinline__ float2 upk(ull v){
    float2 r; asm("mov.b64 {%0,%1}, %2;" : "=f"(r.x), "=f"(r.y) : "l"(v)); return r;
}

// ---------------- zero counters ----------------
__global__ void k_zero_counts(){
    int i = blockIdx.x*256 + threadIdx.x;
    if (i < Nn){ g_deg[i]=0; g_cnt[i]=0; }
}

// ---------------- bond encoder ----------------
__global__ void k_bond(const float* __restrict__ ea, const float* __restrict__ Wbe,
                       const float* __restrict__ bbe){
    __shared__ float sW[EDd*Hd];
    __shared__ float sattr[16*EDd];
    int tid = threadIdx.x;  // 128
    for (int i=tid;i<EDd*Hd;i+=128) sW[i]=Wbe[i];
    float bias = bbe[tid];
    int e0 = blockIdx.x*16;
    for (int i=tid;i<16*EDd;i+=128){
        int ei = e0 + (i>>4);
        sattr[i] = (ei<Ee) ? ea[ei*EDd + (i&15)] : 0.f;
    }
    __syncthreads();
    #pragma unroll 1
    for (int j=0;j<16;j++){
        int e = e0+j;
        if (e>=Ee) break;
        float acc = bias;
        #pragma unroll
        for (int d=0;d<EDd;d++) acc += sattr[j*EDd+d]*sW[d*Hd+tid];
        g_ee[e*Hd+tid] = acc;
    }
}

// ---------------- CSR build on dst ----------------
__global__ void k_hist(const int* __restrict__ dst){
    int e = blockIdx.x*256 + threadIdx.x;
    if (e < Ee) atomicAdd(&g_deg[dst[e]], 1);
}

// parallel scan stage 1: per-block (1024-wide) exclusive scan + block sums
__global__ void k_scan1(){
    __shared__ int s[1024];
    int tid = threadIdx.x;
    int i = blockIdx.x*1024 + tid;
    int v = (i<Nn) ? g_deg[i] : 0;
    s[tid] = v; __syncthreads();
    #pragma unroll
    for (int off=1; off<1024; off<<=1){
        int t = (tid>=off) ? s[tid-off] : 0;
        __syncthreads();
        s[tid] += t;
        __syncthreads();
    }
    if (i<Nn) g_offs[i] = s[tid] - v;   // exclusive within block
    if (tid==1023) g_bsum[blockIdx.x] = s[1023];
}

// stage 2: tiny serial scan of 49 block sums (single thread; ~trivial)
__global__ void k_scan2(){
    if (threadIdx.x==0){
        int acc = 0;
        for (int b=0;b<NBLK_SCAN;b++){ g_boff[b]=acc; acc+=g_bsum[b]; }
        g_boff[NBLK_SCAN]=acc;
        g_offs[Nn]=acc;
    }
}

// stage 3: add block offsets
__global__ void k_scan3(){
    int i = blockIdx.x*1024 + threadIdx.x;
    if (i<Nn) g_offs[i] += g_boff[blockIdx.x];
}

__global__ void k_fill(const int* __restrict__ dst){
    int e = blockIdx.x*256 + threadIdx.x;
    if (e < Ee){
        int d = dst[e];
        int p = atomicAdd(&g_cnt[d], 1);
        g_csr[g_offs[d]+p] = e;
    }
}

// ---------------- graph boundaries (batch is sorted) ----------------
__global__ void k_gstart(const int* __restrict__ batch){
    int g = threadIdx.x;
    if (g > Gg) return;
    int lo = 0, hi = Nn;
    while (lo < hi){
        int mid = (lo+hi) >> 1;
        if (batch[mid] < g) lo = mid+1; else hi = mid;
    }
    g_gstart[g] = lo;
}

// ---------------- aggregation ----------------
__global__ void k_agg(const float* __restrict__ xin, const float* __restrict__ em,
                      const int* __restrict__ src, const float* __restrict__ epsp,
                      int l, float* __restrict__ hout){
    int h = threadIdx.x;
    int n = blockIdx.x;
    float ep = 1.0f + epsp[l];
    int beg = g_offs[n], end = g_offs[n+1];
    float a0 = ep * xin[(0*Nn+n)*Hd+h];
    float a1 = ep * xin[(1*Nn+n)*Hd+h];
    float a2 = ep * xin[(2*Nn+n)*Hd+h];
    float a3 = ep * xin[(3*Nn+n)*Hd+h];
    for (int k=beg; k<end; k++){
        int e = g_csr[k];
        int s = src[e];
        float eeh = g_ee[e*Hd+h];
        float m0 = em[0*Ee+e], m1 = em[1*Ee+e], m2 = em[2*Ee+e], m3 = em[3*Ee+e];
        a0 += gelu_f(xin[(0*Nn+s)*Hd+h] + eeh) * m0;
        a1 += gelu_f(xin[(1*Nn+s)*Hd+h] + eeh) * m1;
        a2 += gelu_f(xin[(2*Nn+s)*Hd+h] + eeh) * m2;
        a3 += gelu_f(xin[(3*Nn+s)*Hd+h] + eeh) * m3;
    }
    hout[(0*Nn+n)*Hd+h] = a0;
    hout[(1*Nn+n)*Hd+h] = a1;
    hout[(2*Nn+n)*Hd+h] = a2;
    hout[(3*Nn+n)*Hd+h] = a3;
}

// ---------------- fused MLP with packed f32x2 FMA ----------------
// out = [gelu]( gelu(in@Wa+ba) @ Wb + bb ); 512 threads, 128-row tile, K=128.
#define SA_LD 132
#define SMEM_MLP ((16384 + 16384 + 128*SA_LD) * 4)

__global__ void __launch_bounds__(512, 1)
k_mlp(const float* __restrict__ in, float* __restrict__ out,
      const float* __restrict__ Wa, const float* __restrict__ ba,
      const float* __restrict__ Wb, const float* __restrict__ bb,
      int rows, int outer_gelu){
    extern __shared__ float smem[];
    float* sWa = smem;              // [128][128]
    float* sWb = smem + 16384;      // [128][128]
    float* sA  = smem + 32768;      // [128][SA_LD]
    const int tid = threadIdx.x;

    {   // weights
        const float4* Wa4 = (const float4*)Wa;
        const float4* Wb4 = (const float4*)Wb;
        float4* sWa4 = (float4*)sWa;
        float4* sWb4 = (float4*)sWb;
        #pragma unroll
        for (int i=tid; i<4096; i+=512){ sWa4[i]=Wa4[i]; sWb4[i]=Wb4[i]; }
    }
    const int base = blockIdx.x*128;
    #pragma unroll
    for (int i=tid; i<128*32; i+=512){
        int m = i>>5, kq = i&31;
        float4 v = make_float4(0.f,0.f,0.f,0.f);
        if (base+m < rows) v = *(const float4*)&in[(base+m)*Hd + kq*4];
        *(float4*)&sA[m*SA_LD + kq*4] = v;
    }
    __syncthreads();

    const int n4 = (tid & 31)*4;
    const int m8 = (tid >> 5)*8;
    const float* sArow = sA + m8*SA_LD;   // warp-uniform (broadcast loads)
    ull accL[8], accH[8];

    // ---- GEMM1 + gelu ----
    {
        float4 bv = *(const float4*)&ba[n4];
        ull bL = pk(bv.x,bv.y), bH = pk(bv.z,bv.w);
        #pragma unroll
        for (int mi=0;mi<8;mi++){ accL[mi]=bL; accH[mi]=bH; }
        #pragma unroll 8
        for (int k=0;k<128;k+=4){
            float4 w0 = *(float4*)&sWa[(k+0)*Hd + n4];
            float4 w1 = *(float4*)&sWa[(k+1)*Hd + n4];
            float4 w2 = *(float4*)&sWa[(k+2)*Hd + n4];
            float4 w3 = *(float4*)&sWa[(k+3)*Hd + n4];
            ull w0L=pk(w0.x,w0.y), w0H=pk(w0.z,w0.w);
            ull w1L=pk(w1.x,w1.y), w1H=pk(w1.z,w1.w);
            ull w2L=pk(w2.x,w2.y), w2H=pk(w2.z,w2.w);
            ull w3L=pk(w3.x,w3.y), w3H=pk(w3.z,w3.w);
            #pragma unroll
            for (int mi=0;mi<8;mi++){
                float4 a = *(float4*)&sArow[mi*SA_LD + k];
                ull ax=pkb(a.x), ay=pkb(a.y), az=pkb(a.z), aw=pkb(a.w);
                fma2(accL[mi], ax, w0L); fma2(accH[mi], ax, w0H);
                fma2(accL[mi], ay, w1L); fma2(accH[mi], ay, w1H);
                fma2(accL[mi], az, w2L); fma2(accH[mi], az, w2H);
                fma2(accL[mi], aw, w3L); fma2(accH[mi], aw, w3H);
            }
        }
    }
    __syncthreads();   // all reads of sA done
    #pragma unroll
    for (int mi=0;mi<8;mi++){
        float2 lo = upk(accL[mi]), hi = upk(accH[mi]);
        *(float4*)&sA[(m8+mi)*SA_LD + n4] =
            make_float4(gelu_f(lo.x), gelu_f(lo.y), gelu_f(hi.x), gelu_f(hi.y));
    }
    __syncthreads();

    // ---- GEMM2 + optional gelu ----
    {
        float4 bv = *(const float4*)&bb[n4];
        ull bL = pk(bv.x,bv.y), bH = pk(bv.z,bv.w);
        #pragma unroll
        for (int mi=0;mi<8;mi++){ accL[mi]=bL; accH[mi]=bH; }
        #pragma unroll 8
        for (int k=0;k<128;k+=4){
            float4 w0 = *(float4*)&sWb[(k+0)*Hd + n4];
            float4 w1 = *(float4*)&sWb[(k+1)*Hd + n4];
            float4 w2 = *(float4*)&sWb[(k+2)*Hd + n4];
            float4 w3 = *(float4*)&sWb[(k+3)*Hd + n4];
            ull w0L=pk(w0.x,w0.y), w0H=pk(w0.z,w0.w);
            ull w1L=pk(w1.x,w1.y), w1H=pk(w1.z,w1.w);
            ull w2L=pk(w2.x,w2.y), w2H=pk(w2.z,w2.w);
            ull w3L=pk(w3.x,w3.y), w3H=pk(w3.z,w3.w);
            #pragma unroll
            for (int mi=0;mi<8;mi++){
                float4 a = *(float4*)&sArow[mi*SA_LD + k];
                ull ax=pkb(a.x), ay=pkb(a.y), az=pkb(a.z), aw=pkb(a.w);
                fma2(accL[mi], ax, w0L); fma2(accH[mi], ax, w0H);
                fma2(accL[mi], ay, w1L); fma2(accH[mi], ay, w1H);
                fma2(accL[mi], az, w2L); fma2(accH[mi], az, w2H);
                fma2(accL[mi], aw, w3L); fma2(accH[mi], aw, w3H);
            }
        }
        #pragma unroll
        for (int mi=0;mi<8;mi++){
            if (base+m8+mi < rows){
                float2 lo = upk(accL[mi]), hi = upk(accH[mi]);
                float4 o;
                if (outer_gelu)
                    o = make_float4(gelu_f(lo.x), gelu_f(lo.y), gelu_f(hi.x), gelu_f(hi.y));
                else
                    o = make_float4(lo.x, lo.y, hi.x, hi.y);
                *(float4*)&out[(base+m8+mi)*Hd + n4] = o;
            }
        }
    }
}

// ---------------- masked mean pool, 4-way node split per block ----------------
__global__ void k_pool(const float* __restrict__ y, const float* __restrict__ nm,
                       float* __restrict__ out){
    __shared__ float snum[512];
    __shared__ float sden[4];
    int f = threadIdx.x & 127;
    int slice = threadIdx.x >> 7;     // 0..3
    int g = blockIdx.x, c = blockIdx.y;
    int beg = g_gstart[g], end = g_gstart[g+1];
    float num = 0.f, den = 0.f;
    for (int n=beg+slice; n<end; n+=4){
        float m = nm[c*Nn+n];
        num += y[(c*Nn+n)*Hd+f]*m;
        den += m;
    }
    snum[threadIdx.x] = num;
    if (f==0) sden[slice] = den;
    __syncthreads();
    if (slice==0){
        float tot = snum[f] + snum[128+f] + snum[256+f] + snum[384+f];
        float d = sden[0]+sden[1]+sden[2]+sden[3] + 1e-7f;
        out[(g*Cc+c)*Hd+f] = tot / d;
    }
}

// ---------------- launch ----------------
extern "C" void kernel_launch(void* const* d_in, const int* in_sizes, int n_in,
                              void* d_out, int out_size){
    const float* x    = (const float*)d_in[0];
    const int*  batch = (const int*)d_in[1];
    const int*  eidx  = (const int*)d_in[2];
    const float* ea   = (const float*)d_in[3];
    const float* nm   = (const float*)d_in[4];
    const float* em   = (const float*)d_in[5];
    const float* Wbe  = (const float*)d_in[6];
    const float* bbe  = (const float*)d_in[7];
    const float* eps  = (const float*)d_in[8];
    const float* W1   = (const float*)d_in[9];
    const float* b1   = (const float*)d_in[10];
    const float* W2   = (const float*)d_in[11];
    const float* b2   = (const float*)d_in[12];
    const float* Wm1  = (const float*)d_in[13];
    const float* bm1  = (const float*)d_in[14];
    const float* Wm2  = (const float*)d_in[15];
    const float* bm2  = (const float*)d_in[16];
    float* out = (float*)d_out;

    const int* src = eidx;
    const int* dst = eidx + Ee;

    float *bufA, *bufB;
    cudaGetSymbolAddress((void**)&bufA, g_bufA);
    cudaGetSymbolAddress((void**)&bufB, g_bufB);
    cudaFuncSetAttribute(k_mlp, cudaFuncAttributeMaxDynamicSharedMemorySize, SMEM_MLP);

    const int mlp_grid = (NROWS + 127)/128;

    k_zero_counts<<<(Nn+255)/256, 256>>>();
    k_bond<<<(Ee+15)/16, 128>>>(ea, Wbe, bbe);
    k_hist<<<(Ee+255)/256, 256>>>(dst);
    k_scan1<<<NBLK_SCAN, 1024>>>();
    k_scan2<<<1, 32>>>();
    k_scan3<<<NBLK_SCAN, 1024>>>();
    k_fill<<<(Ee+255)/256, 256>>>(dst);
    k_gstart<<<1, 128>>>(batch);

    // layer 0
    k_agg<<<Nn, 128>>>(x, em, src, eps, 0, bufA);
    k_mlp<<<mlp_grid, 512, SMEM_MLP>>>(bufA, bufB, W1, b1, W2, b2, NROWS, 1);
    // layer 1
    k_agg<<<Nn, 128>>>(bufB, em, src, eps, 1, bufA);
    k_mlp<<<mlp_grid, 512, SMEM_MLP>>>(bufA, bufB, W1 + Hd*Hd, b1 + Hd, W2 + Hd*Hd, b2 + Hd, NROWS, 1);
    // final MLP (no outer gelu)
    k_mlp<<<mlp_grid, 512, SMEM_MLP>>>(bufB, bufA, Wm1, bm1, Wm2, bm2, NROWS, 0);
    // pool
    k_pool<<<dim3(Gg, Cc), 512>>>(bufA, nm, out);
}

// round 7
// speedup vs baseline: 1.4147x; 1.2338x over previous
#include <cuda_runtime.h>
#include <cuda_bf16.h>
#include <cstdint>
#include <cstring>
#include <math.h>

#define Nn 50000
#define Ee 200000
#define Hd 128
#define Cc 4
#define Gg 64
#define EDd 16
#define NROWS (Cc*Nn)   // 200000
#define NBLK_SCAN ((Nn + 1023)/1024)   // 49

// ---------------- scratch (device globals; no allocation allowed) ----------------
__device__ __align__(128) float g_ee[Ee*Hd];
__device__ __align__(128) float g_bufA[NROWS*Hd];
__device__ __align__(128) float g_bufB[NROWS*Hd];
__device__ int g_deg[Nn];
__device__ int g_offs[Nn+1];
__device__ int g_cnt[Nn];
__device__ int g_csr[Ee];
__device__ int g_gstart[Gg+1];
__device__ int g_bsum[NBLK_SCAN];
__device__ int g_boff[NBLK_SCAN+1];
// pre-split weights: 6 matrices x {hi,lo} x 16384 bf16, row-major [k][n]
__device__ __align__(128) __nv_bfloat16 g_wsp[6*2*16384];

__device__ __forceinline__ float gelu_f(float v){
    return 0.5f*v*(1.0f+erff(v*0.7071067811865475f));
}

__device__ __forceinline__ uint32_t smem_u32(const void* p){
    uint32_t a;
    asm("{ .reg .u64 t; cvta.to.shared.u64 t, %1; cvt.u32.u64 %0, t; }" : "=r"(a) : "l"(p));
    return a;
}
__device__ __forceinline__ void ldsm_x4(uint32_t& r0, uint32_t& r1, uint32_t& r2, uint32_t& r3, uint32_t addr){
    asm volatile("ldmatrix.sync.aligned.m8n8.x4.shared.b16 {%0,%1,%2,%3}, [%4];"
        : "=r"(r0), "=r"(r1), "=r"(r2), "=r"(r3) : "r"(addr));
}
__device__ __forceinline__ void ldsm_x2t(uint32_t& r0, uint32_t& r1, uint32_t addr){
    asm volatile("ldmatrix.sync.aligned.m8n8.x2.trans.shared.b16 {%0,%1}, [%2];"
        : "=r"(r0), "=r"(r1) : "r"(addr));
}
__device__ __forceinline__ void mma_bf16(float* c, const uint32_t* a, uint32_t b0, uint32_t b1){
    asm volatile("mma.sync.aligned.m16n8k16.row.col.f32.bf16.bf16.f32 "
        "{%0,%1,%2,%3},{%4,%5,%6,%7},{%8,%9},{%0,%1,%2,%3};"
        : "+f"(c[0]), "+f"(c[1]), "+f"(c[2]), "+f"(c[3])
        : "r"(a[0]), "r"(a[1]), "r"(a[2]), "r"(a[3]), "r"(b0), "r"(b1));
}
__device__ __forceinline__ uint32_t pack_bf16(float a, float b){
    __nv_bfloat162 t = __floats2bfloat162_rn(a, b);
    uint32_t u; memcpy(&u, &t, 4); return u;
}

// ---------------- weight prep: split fp32 W[k][n] -> bf16 hi/lo row-major ----------------
__global__ void k_prepw(const float* __restrict__ W, __nv_bfloat16* __restrict__ hi,
                        __nv_bfloat16* __restrict__ lo){
    int idx = blockIdx.x*256 + threadIdx.x;
    if (idx >= 16384) return;
    float w = W[idx];
    __nv_bfloat16 h = __float2bfloat16(w);
    __nv_bfloat16 l = __float2bfloat16(w - __bfloat162float(h));
    hi[idx] = h;
    lo[idx] = l;
}

// ---------------- mma.sync fused MLP ----------------
// smem: 6 bf16 buffers [128][LDA]: A_hi, A_lo, Wa_hi, Wa_lo, Wb_hi, Wb_lo
#define LDA 136
#define SM_AH  0
#define SM_AL  (128*LDA)
#define SM_WAH (2*128*LDA)
#define SM_WAL (3*128*LDA)
#define SM_WBH (4*128*LDA)
#define SM_WBL (5*128*LDA)
#define SMEM_MMA (6*128*LDA*2)

__device__ __forceinline__ void gemm_128(uint32_t sb, int a_h, int a_l, int w_h, int w_l,
                                         float acc[16][4], int m0, int lane){
    // A ldmatrix address: row = m0 + (lane&15), k-block col = (lane>>4)*8
    uint32_t aah = sb + 2u*((uint32_t)(a_h + (m0 + (lane&15))*LDA + (lane>>4)*8));
    uint32_t aal = sb + 2u*((uint32_t)(a_l + (m0 + (lane&15))*LDA + (lane>>4)*8));
    // B ldmatrix address rows: k = kb*16 + (lane&15), col n0
    uint32_t bwh = sb + 2u*((uint32_t)(w_h + (lane&15)*LDA));
    uint32_t bwl = sb + 2u*((uint32_t)(w_l + (lane&15)*LDA));
    #pragma unroll 1
    for (int kb = 0; kb < 8; kb++){
        uint32_t ah[4], al[4];
        ldsm_x4(ah[0], ah[1], ah[2], ah[3], aah + kb*32);
        ldsm_x4(al[0], al[1], al[2], al[3], aal + kb*32);
        uint32_t bh_row = bwh + kb*(16*LDA*2);
        uint32_t bl_row = bwl + kb*(16*LDA*2);
        #pragma unroll
        for (int nt = 0; nt < 16; nt++){
            uint32_t bh0, bh1, bl0, bl1;
            ldsm_x2t(bh0, bh1, bh_row + nt*16);
            ldsm_x2t(bl0, bl1, bl_row + nt*16);
            mma_bf16(acc[nt], ah, bh0, bh1);
            mma_bf16(acc[nt], ah, bl0, bl1);
            mma_bf16(acc[nt], al, bh0, bh1);
        }
    }
}

__global__ void __launch_bounds__(256, 1)
k_mlp_mma(const float* __restrict__ in, float* __restrict__ out,
          const __nv_bfloat16* __restrict__ wa_hi, const __nv_bfloat16* __restrict__ wa_lo,
          const __nv_bfloat16* __restrict__ wb_hi, const __nv_bfloat16* __restrict__ wb_lo,
          const float* __restrict__ ba, const float* __restrict__ bb,
          int rows, int outer_gelu){
    extern __shared__ __nv_bfloat16 sm[];
    const uint32_t sb = smem_u32(sm);
    const int tid = threadIdx.x;
    const int base = blockIdx.x*128;

    // copy weights gmem -> padded smem (uint4 = 8 bf16)
    {
        const uint4* s0 = (const uint4*)wa_hi; const uint4* s1 = (const uint4*)wa_lo;
        const uint4* s2 = (const uint4*)wb_hi; const uint4* s3 = (const uint4*)wb_lo;
        #pragma unroll
        for (int i = tid; i < 2048; i += 256){
            int row = i >> 4, c8 = (i & 15)*8;
            int d = row*LDA + c8;
            *(uint4*)&sm[SM_WAH + d] = s0[i];
            *(uint4*)&sm[SM_WAL + d] = s1[i];
            *(uint4*)&sm[SM_WBH + d] = s2[i];
            *(uint4*)&sm[SM_WBL + d] = s3[i];
        }
    }
    // load + hi/lo split A tile
    {
        int row = tid >> 1, ch = (tid & 1)*64;
        bool valid = (base + row) < rows;
        const float* ip = in + (size_t)(base+row)*Hd + ch;
        #pragma unroll
        for (int j = 0; j < 64; j += 4){
            float4 v = valid ? *(const float4*)(ip + j) : make_float4(0.f,0.f,0.f,0.f);
            __nv_bfloat16 h0=__float2bfloat16(v.x), h1=__float2bfloat16(v.y);
            __nv_bfloat16 h2=__float2bfloat16(v.z), h3=__float2bfloat16(v.w);
            float r0=v.x-__bfloat162float(h0), r1=v.y-__bfloat162float(h1);
            float r2=v.z-__bfloat162float(h2), r3=v.w-__bfloat162float(h3);
            int d = row*LDA + ch + j;
            __nv_bfloat162 hh0; hh0.x=h0; hh0.y=h1;  __nv_bfloat162 hh1; hh1.x=h2; hh1.y=h3;
            uint32_t u0, u1; memcpy(&u0,&hh0,4); memcpy(&u1,&hh1,4);
            *(uint32_t*)&sm[SM_AH + d]     = u0;
            *(uint32_t*)&sm[SM_AH + d + 2] = u1;
            *(uint32_t*)&sm[SM_AL + d]     = pack_bf16(r0, r1);
            *(uint32_t*)&sm[SM_AL + d + 2] = pack_bf16(r2, r3);
        }
    }
    __syncthreads();

    const int w = tid >> 5, lane = tid & 31;
    const int m0 = w*16;
    const int grp = lane >> 2, quad = lane & 3;
    float acc[16][4];

    // ---- GEMM1 ----
    #pragma unroll
    for (int nt = 0; nt < 16; nt++){ acc[nt][0]=0.f; acc[nt][1]=0.f; acc[nt][2]=0.f; acc[nt][3]=0.f; }
    gemm_128(sb, SM_AH, SM_AL, SM_WAH, SM_WAL, acc, m0, lane);
    __syncthreads();   // all A reads done before overwrite

    // epilogue 1: +bias, gelu, re-split into A buffers
    {
        int r0 = m0 + grp, r1 = r0 + 8;
        #pragma unroll
        for (int nt = 0; nt < 16; nt++){
            int n = nt*8 + quad*2;
            float b0 = ba[n], b1 = ba[n+1];
            float v00 = gelu_f(acc[nt][0] + b0), v01 = gelu_f(acc[nt][1] + b1);
            float v10 = gelu_f(acc[nt][2] + b0), v11 = gelu_f(acc[nt][3] + b1);
            __nv_bfloat16 h00=__float2bfloat16(v00), h01=__float2bfloat16(v01);
            __nv_bfloat16 h10=__float2bfloat16(v10), h11=__float2bfloat16(v11);
            float l00=v00-__bfloat162float(h00), l01=v01-__bfloat162float(h01);
            float l10=v10-__bfloat162float(h10), l11=v11-__bfloat162float(h11);
            __nv_bfloat162 p0; p0.x=h00; p0.y=h01;  __nv_bfloat162 p1; p1.x=h10; p1.y=h11;
            uint32_t u0, u1; memcpy(&u0,&p0,4); memcpy(&u1,&p1,4);
            *(uint32_t*)&sm[SM_AH + r0*LDA + n] = u0;
            *(uint32_t*)&sm[SM_AH + r1*LDA + n] = u1;
            *(uint32_t*)&sm[SM_AL + r0*LDA + n] = pack_bf16(l00, l01);
            *(uint32_t*)&sm[SM_AL + r1*LDA + n] = pack_bf16(l10, l11);
        }
    }
    __syncthreads();

    // ---- GEMM2 ----
    #pragma unroll
    for (int nt = 0; nt < 16; nt++){ acc[nt][0]=0.f; acc[nt][1]=0.f; acc[nt][2]=0.f; acc[nt][3]=0.f; }
    gemm_128(sb, SM_AH, SM_AL, SM_WBH, SM_WBL, acc, m0, lane);

    // epilogue 2: +bias, optional gelu, store fp32
    {
        int r0 = m0 + grp, r1 = r0 + 8;
        bool v0 = (base + r0) < rows, v1 = (base + r1) < rows;
        #pragma unroll
        for (int nt = 0; nt < 16; nt++){
            int n = nt*8 + quad*2;
            float b0 = bb[n], b1 = bb[n+1];
            float o00 = acc[nt][0] + b0, o01 = acc[nt][1] + b1;
            float o10 = acc[nt][2] + b0, o11 = acc[nt][3] + b1;
            if (outer_gelu){ o00=gelu_f(o00); o01=gelu_f(o01); o10=gelu_f(o10); o11=gelu_f(o11); }
            if (v0) *(float2*)&out[(size_t)(base+r0)*Hd + n] = make_float2(o00, o01);
            if (v1) *(float2*)&out[(size_t)(base+r1)*Hd + n] = make_float2(o10, o11);
        }
    }
}

// ---------------- zero counters ----------------
__global__ void k_zero_counts(){
    int i = blockIdx.x*256 + threadIdx.x;
    if (i < Nn){ g_deg[i]=0; g_cnt[i]=0; }
}

// ---------------- bond encoder ----------------
__global__ void k_bond(const float* __restrict__ ea, const float* __restrict__ Wbe,
                       const float* __restrict__ bbe){
    __shared__ float sW[EDd*Hd];
    __shared__ float sattr[16*EDd];
    int tid = threadIdx.x;  // 128
    for (int i=tid;i<EDd*Hd;i+=128) sW[i]=Wbe[i];
    float bias = bbe[tid];
    int e0 = blockIdx.x*16;
    for (int i=tid;i<16*EDd;i+=128){
        int ei = e0 + (i>>4);
        sattr[i] = (ei<Ee) ? ea[ei*EDd + (i&15)] : 0.f;
    }
    __syncthreads();
    #pragma unroll 1
    for (int j=0;j<16;j++){
        int e = e0+j;
        if (e>=Ee) break;
        float acc = bias;
        #pragma unroll
        for (int d=0;d<EDd;d++) acc += sattr[j*EDd+d]*sW[d*Hd+tid];
        g_ee[e*Hd+tid] = acc;
    }
}

// ---------------- CSR build on dst ----------------
__global__ void k_hist(const int* __restrict__ dst){
    int e = blockIdx.x*256 + threadIdx.x;
    if (e < Ee) atomicAdd(&g_deg[dst[e]], 1);
}

__global__ void k_scan1(){
    __shared__ int s[1024];
    int tid = threadIdx.x;
    int i = blockIdx.x*1024 + tid;
    int v = (i<Nn) ? g_deg[i] : 0;
    s[tid] = v; __syncthreads();
    #pragma unroll
    for (int off=1; off<1024; off<<=1){
        int t = (tid>=off) ? s[tid-off] : 0;
        __syncthreads();
        s[tid] += t;
        __syncthreads();
    }
    if (i<Nn) g_offs[i] = s[tid] - v;
    if (tid==1023) g_bsum[blockIdx.x] = s[1023];
}

__global__ void k_scan2(){
    if (threadIdx.x==0){
        int acc = 0;
        for (int b=0;b<NBLK_SCAN;b++){ g_boff[b]=acc; acc+=g_bsum[b]; }
        g_boff[NBLK_SCAN]=acc;
        g_offs[Nn]=acc;
    }
}

__global__ void k_scan3(){
    int i = blockIdx.x*1024 + threadIdx.x;
    if (i<Nn) g_offs[i] += g_boff[blockIdx.x];
}

__global__ void k_fill(const int* __restrict__ dst){
    int e = blockIdx.x*256 + threadIdx.x;
    if (e < Ee){
        int d = dst[e];
        int p = atomicAdd(&g_cnt[d], 1);
        g_csr[g_offs[d]+p] = e;
    }
}

// ---------------- graph boundaries ----------------
__global__ void k_gstart(const int* __restrict__ batch){
    int g = threadIdx.x;
    if (g > Gg) return;
    int lo = 0, hi = Nn;
    while (lo < hi){
        int mid = (lo+hi) >> 1;
        if (batch[mid] < g) lo = mid+1; else hi = mid;
    }
    g_gstart[g] = lo;
}

// ---------------- aggregation ----------------
__global__ void k_agg(const float* __restrict__ xin, const float* __restrict__ em,
                      const int* __restrict__ src, const float* __restrict__ epsp,
                      int l, float* __restrict__ hout){
    int h = threadIdx.x;
    int n = blockIdx.x;
    float ep = 1.0f + epsp[l];
    int beg = g_offs[n], end = g_offs[n+1];
    float a0 = ep * xin[(0*Nn+n)*Hd+h];
    float a1 = ep * xin[(1*Nn+n)*Hd+h];
    float a2 = ep * xin[(2*Nn+n)*Hd+h];
    float a3 = ep * xin[(3*Nn+n)*Hd+h];
    for (int k=beg; k<end; k++){
        int e = g_csr[k];
        int s = src[e];
        float eeh = g_ee[e*Hd+h];
        float m0 = em[0*Ee+e], m1 = em[1*Ee+e], m2 = em[2*Ee+e], m3 = em[3*Ee+e];
        a0 += gelu_f(xin[(0*Nn+s)*Hd+h] + eeh) * m0;
        a1 += gelu_f(xin[(1*Nn+s)*Hd+h] + eeh) * m1;
        a2 += gelu_f(xin[(2*Nn+s)*Hd+h] + eeh) * m2;
        a3 += gelu_f(xin[(3*Nn+s)*Hd+h] + eeh) * m3;
    }
    hout[(0*Nn+n)*Hd+h] = a0;
    hout[(1*Nn+n)*Hd+h] = a1;
    hout[(2*Nn+n)*Hd+h] = a2;
    hout[(3*Nn+n)*Hd+h] = a3;
}

// ---------------- masked mean pool ----------------
__global__ void k_pool(const float* __restrict__ y, const float* __restrict__ nm,
                       float* __restrict__ out){
    __shared__ float snum[512];
    __shared__ float sden[4];
    int f = threadIdx.x & 127;
    int slice = threadIdx.x >> 7;
    int g = blockIdx.x, c = blockIdx.y;
    int beg = g_gstart[g], end = g_gstart[g+1];
    float num = 0.f, den = 0.f;
    for (int n=beg+slice; n<end; n+=4){
        float m = nm[c*Nn+n];
        num += y[(c*Nn+n)*Hd+f]*m;
        den += m;
    }
    snum[threadIdx.x] = num;
    if (f==0) sden[slice] = den;
    __syncthreads();
    if (slice==0){
        float tot = snum[f] + snum[128+f] + snum[256+f] + snum[384+f];
        float d = sden[0]+sden[1]+sden[2]+sden[3] + 1e-7f;
        out[(g*Cc+c)*Hd+f] = tot / d;
    }
}

// ---------------- launch ----------------
extern "C" void kernel_launch(void* const* d_in, const int* in_sizes, int n_in,
                              void* d_out, int out_size){
    const float* x    = (const float*)d_in[0];
    const int*  batch = (const int*)d_in[1];
    const int*  eidx  = (const int*)d_in[2];
    const float* ea   = (const float*)d_in[3];
    const float* nm   = (const float*)d_in[4];
    const float* em   = (const float*)d_in[5];
    const float* Wbe  = (const float*)d_in[6];
    const float* bbe  = (const float*)d_in[7];
    const float* eps  = (const float*)d_in[8];
    const float* W1   = (const float*)d_in[9];
    const float* b1   = (const float*)d_in[10];
    const float* W2   = (const float*)d_in[11];
    const float* b2   = (const float*)d_in[12];
    const float* Wm1  = (const float*)d_in[13];
    const float* bm1  = (const float*)d_in[14];
    const float* Wm2  = (const float*)d_in[15];
    const float* bm2  = (const float*)d_in[16];
    float* out = (float*)d_out;

    const int* src = eidx;
    const int* dst = eidx + Ee;

    float *bufA, *bufB;
    __nv_bfloat16* wsp;
    cudaGetSymbolAddress((void**)&bufA, g_bufA);
    cudaGetSymbolAddress((void**)&bufB, g_bufB);
    cudaGetSymbolAddress((void**)&wsp, g_wsp);
    cudaFuncSetAttribute(k_mlp_mma, cudaFuncAttributeMaxDynamicSharedMemorySize, SMEM_MMA);

    // weight prep (mats: 0=W1[0],1=W2[0],2=W1[1],3=W2[1],4=Wm1,5=Wm2)
    const float* wsrc[6] = {W1, W2, W1 + Hd*Hd, W2 + Hd*Hd, Wm1, Wm2};
    for (int m2 = 0; m2 < 6; m2++)
        k_prepw<<<64, 256>>>(wsrc[m2], wsp + (m2*2+0)*16384, wsp + (m2*2+1)*16384);

    k_zero_counts<<<(Nn+255)/256, 256>>>();
    k_bond<<<(Ee+15)/16, 128>>>(ea, Wbe, bbe);
    k_hist<<<(Ee+255)/256, 256>>>(dst);
    k_scan1<<<NBLK_SCAN, 1024>>>();
    k_scan2<<<1, 32>>>();
    k_scan3<<<NBLK_SCAN, 1024>>>();
    k_fill<<<(Ee+255)/256, 256>>>(dst);
    k_gstart<<<1, 128>>>(batch);

    const int mlp_grid = (NROWS + 127)/128;

    // layer 0
    k_agg<<<Nn, 128>>>(x, em, src, eps, 0, bufA);
    k_mlp_mma<<<mlp_grid, 256, SMEM_MMA>>>(bufA, bufB,
        wsp + 0*16384, wsp + 1*16384, wsp + 2*16384, wsp + 3*16384, b1, b2, NROWS, 1);
    // layer 1
    k_agg<<<Nn, 128>>>(bufB, em, src, eps, 1, bufA);
    k_mlp_mma<<<mlp_grid, 256, SMEM_MMA>>>(bufA, bufB,
        wsp + 4*16384, wsp + 5*16384, wsp + 6*16384, wsp + 7*16384, b1 + Hd, b2 + Hd, NROWS, 1);
    // final MLP (no outer gelu)
    k_mlp_mma<<<mlp_grid, 256, SMEM_MMA>>>(bufB, bufA,
        wsp + 8*16384, wsp + 9*16384, wsp + 10*16384, wsp + 11*16384, bm1, bm2, NROWS, 0);
    // pool
    k_pool<<<dim3(Gg, Cc), 512>>>(bufA, nm, out);
}

// round 8
// speedup vs baseline: 1.6557x; 1.1704x over previous
#include <cuda_runtime.h>
#include <cuda_fp16.h>
#include <cstdint>
#include <cstring>
#include <math.h>

#define Nn 50000
#define Ee 200000
#define Hd 128
#define Cc 4
#define Gg 64
#define EDd 16
#define NROWS (Cc*Nn)   // 200000
#define NBLK_SCAN ((Nn + 1023)/1024)   // 49

// ---------------- scratch (device globals; no allocation allowed) ----------------
__device__ __align__(128) float g_ee[Ee*Hd];
__device__ __align__(128) float g_bufA[NROWS*Hd];
__device__ __align__(128) float g_bufB[NROWS*Hd];
__device__ int g_deg[Nn];
__device__ int g_offs[Nn+1];
__device__ int g_cnt[Nn];
__device__ int g_csr[Ee];
__device__ int g_gstart[Gg+1];
__device__ int g_bsum[NBLK_SCAN];
__device__ int g_boff[NBLK_SCAN+1];
// pre-split weights: 6 matrices x {hi,lo} x 16384 fp16, row-major [k][n]
__device__ __align__(128) __half g_wsp[6*2*16384];

__device__ __forceinline__ float gelu_f(float v){
    return 0.5f*v*(1.0f+erff(v*0.7071067811865475f));
}

__device__ __forceinline__ uint32_t smem_u32(const void* p){
    uint32_t a;
    asm("{ .reg .u64 t; cvta.to.shared.u64 t, %1; cvt.u32.u64 %0, t; }" : "=r"(a) : "l"(p));
    return a;
}
__device__ __forceinline__ void ldsm_x4(uint32_t& r0, uint32_t& r1, uint32_t& r2, uint32_t& r3, uint32_t addr){
    asm volatile("ldmatrix.sync.aligned.m8n8.x4.shared.b16 {%0,%1,%2,%3}, [%4];"
        : "=r"(r0), "=r"(r1), "=r"(r2), "=r"(r3) : "r"(addr));
}
__device__ __forceinline__ void ldsm_x2t(uint32_t& r0, uint32_t& r1, uint32_t addr){
    asm volatile("ldmatrix.sync.aligned.m8n8.x2.trans.shared.b16 {%0,%1}, [%2];"
        : "=r"(r0), "=r"(r1) : "r"(addr));
}
__device__ __forceinline__ void mma_fp16(float* c, const uint32_t* a, uint32_t b0, uint32_t b1){
    asm volatile("mma.sync.aligned.m16n8k16.row.col.f32.f16.f16.f32 "
        "{%0,%1,%2,%3},{%4,%5,%6,%7},{%8,%9},{%0,%1,%2,%3};"
        : "+f"(c[0]), "+f"(c[1]), "+f"(c[2]), "+f"(c[3])
        : "r"(a[0]), "r"(a[1]), "r"(a[2]), "r"(a[3]), "r"(b0), "r"(b1));
}
__device__ __forceinline__ uint32_t pack_h2(float a, float b){
    __half2 t = __floats2half2_rn(a, b);
    uint32_t u; memcpy(&u, &t, 4); return u;
}

// ---------------- weight prep: split fp32 W[k][n] -> fp16 hi/lo row-major (all 6 mats) ----------------
__global__ void k_prepw_all(const float* __restrict__ W1, const float* __restrict__ W2,
                            const float* __restrict__ Wm1, const float* __restrict__ Wm2,
                            __half* __restrict__ outw){
    int mat = blockIdx.y;
    const float* src;
    switch (mat){
        case 0: src = W1;          break;
        case 1: src = W2;          break;
        case 2: src = W1 + 16384;  break;
        case 3: src = W2 + 16384;  break;
        case 4: src = Wm1;         break;
        default: src = Wm2;        break;
    }
    int idx = blockIdx.x*256 + threadIdx.x;
    if (idx >= 16384) return;
    float w = src[idx];
    __half h = __float2half_rn(w);
    __half l = __float2half_rn(w - __half2float(h));
    outw[(mat*2+0)*16384 + idx] = h;
    outw[(mat*2+1)*16384 + idx] = l;
}

// ---------------- mma.sync fused MLP (fp16, 2-term: A*Wh + A*Wl) ----------------
// smem: 5 fp16 buffers [128][LDA]: A, Wa_hi, Wa_lo, Wb_hi, Wb_lo
#define LDA 136
#define SM_A   0
#define SM_WAH (128*LDA)
#define SM_WAL (2*128*LDA)
#define SM_WBH (3*128*LDA)
#define SM_WBL (4*128*LDA)
#define SMEM_MMA (5*128*LDA*2)

// warp tile: 32 rows x 64 cols. acc[mt][nt][4], mt in {0,1}, nt in 0..7
__device__ __forceinline__ void gemm_2t(uint32_t sb, int w_h, int w_l,
                                        float acc[2][8][4], int m0, int wn, int lane){
    uint32_t aaddr  = sb + 2u*((uint32_t)(SM_A + (m0 + (lane&15))*LDA + (lane>>4)*8));
    uint32_t baddrh = sb + 2u*((uint32_t)(w_h + (lane&15)*LDA + wn*64));
    uint32_t baddrl = sb + 2u*((uint32_t)(w_l + (lane&15)*LDA + wn*64));
    #pragma unroll
    for (int kb = 0; kb < 8; kb++){
        uint32_t a0[4], a1[4];
        ldsm_x4(a0[0], a0[1], a0[2], a0[3], aaddr + kb*32);
        ldsm_x4(a1[0], a1[1], a1[2], a1[3], aaddr + 16*LDA*2 + kb*32);
        uint32_t bstep = (uint32_t)kb*(16*LDA*2);
        #pragma unroll
        for (int nt = 0; nt < 8; nt++){
            uint32_t bh0, bh1, bl0, bl1;
            ldsm_x2t(bh0, bh1, baddrh + bstep + nt*16);
            ldsm_x2t(bl0, bl1, baddrl + bstep + nt*16);
            mma_fp16(acc[0][nt], a0, bh0, bh1);
            mma_fp16(acc[0][nt], a0, bl0, bl1);
            mma_fp16(acc[1][nt], a1, bh0, bh1);
            mma_fp16(acc[1][nt], a1, bl0, bl1);
        }
    }
}

__global__ void __launch_bounds__(256, 1)
k_mlp_mma(const float* __restrict__ in, float* __restrict__ out,
          const __half* __restrict__ wa_hi, const __half* __restrict__ wa_lo,
          const __half* __restrict__ wb_hi, const __half* __restrict__ wb_lo,
          const float* __restrict__ ba, const float* __restrict__ bb,
          int rows, int outer_gelu){
    extern __shared__ __half sm[];
    const uint32_t sb = smem_u32(sm);
    const int tid = threadIdx.x;
    const int base = blockIdx.x*128;

    // copy weights gmem -> padded smem (uint4 = 8 halves)
    {
        const uint4* s0 = (const uint4*)wa_hi; const uint4* s1 = (const uint4*)wa_lo;
        const uint4* s2 = (const uint4*)wb_hi; const uint4* s3 = (const uint4*)wb_lo;
        #pragma unroll
        for (int i = tid; i < 2048; i += 256){
            int row = i >> 4, c8 = (i & 15)*8;
            int d = row*LDA + c8;
            *(uint4*)&sm[SM_WAH + d] = s0[i];
            *(uint4*)&sm[SM_WAL + d] = s1[i];
            *(uint4*)&sm[SM_WBH + d] = s2[i];
            *(uint4*)&sm[SM_WBL + d] = s3[i];
        }
    }
    // load A tile as fp16
    {
        int row = tid >> 1, ch = (tid & 1)*64;
        bool valid = (base + row) < rows;
        const float* ip = in + (size_t)(base+row)*Hd + ch;
        #pragma unroll
        for (int j = 0; j < 64; j += 4){
            float4 v = valid ? *(const float4*)(ip + j) : make_float4(0.f,0.f,0.f,0.f);
            int d = row*LDA + ch + j;
            *(uint32_t*)&sm[SM_A + d]     = pack_h2(v.x, v.y);
            *(uint32_t*)&sm[SM_A + d + 2] = pack_h2(v.z, v.w);
        }
    }
    __syncthreads();

    const int w = tid >> 5, lane = tid & 31;
    const int wm = w & 3, wn = w >> 2;
    const int m0 = wm*32;
    const int grp = lane >> 2, quad = lane & 3;
    float acc[2][8][4];

    // ---- GEMM1 ----
    #pragma unroll
    for (int mt = 0; mt < 2; mt++)
        #pragma unroll
        for (int nt = 0; nt < 8; nt++){ acc[mt][nt][0]=0.f; acc[mt][nt][1]=0.f; acc[mt][nt][2]=0.f; acc[mt][nt][3]=0.f; }
    gemm_2t(sb, SM_WAH, SM_WAL, acc, m0, wn, lane);
    __syncthreads();   // all A reads done before overwrite

    // epilogue 1: +bias, gelu, back to A as fp16
    #pragma unroll
    for (int mt = 0; mt < 2; mt++){
        int r0 = m0 + mt*16 + grp, r1 = r0 + 8;
        #pragma unroll
        for (int nt = 0; nt < 8; nt++){
            int n = wn*64 + nt*8 + quad*2;
            float b0 = ba[n], b1 = ba[n+1];
            float v00 = gelu_f(acc[mt][nt][0] + b0), v01 = gelu_f(acc[mt][nt][1] + b1);
            float v10 = gelu_f(acc[mt][nt][2] + b0), v11 = gelu_f(acc[mt][nt][3] + b1);
            *(uint32_t*)&sm[SM_A + r0*LDA + n] = pack_h2(v00, v01);
            *(uint32_t*)&sm[SM_A + r1*LDA + n] = pack_h2(v10, v11);
        }
    }
    __syncthreads();

    // ---- GEMM2 ----
    #pragma unroll
    for (int mt = 0; mt < 2; mt++)
        #pragma unroll
        for (int nt = 0; nt < 8; nt++){ acc[mt][nt][0]=0.f; acc[mt][nt][1]=0.f; acc[mt][nt][2]=0.f; acc[mt][nt][3]=0.f; }
    gemm_2t(sb, SM_WBH, SM_WBL, acc, m0, wn, lane);

    // epilogue 2: +bias, optional gelu, store fp32
    #pragma unroll
    for (int mt = 0; mt < 2; mt++){
        int r0 = m0 + mt*16 + grp, r1 = r0 + 8;
        bool v0 = (base + r0) < rows, v1 = (base + r1) < rows;
        #pragma unroll
        for (int nt = 0; nt < 8; nt++){
            int n = wn*64 + nt*8 + quad*2;
            float b0 = bb[n], b1 = bb[n+1];
            float o00 = acc[mt][nt][0] + b0, o01 = acc[mt][nt][1] + b1;
            float o10 = acc[mt][nt][2] + b0, o11 = acc[mt][nt][3] + b1;
            if (outer_gelu){ o00=gelu_f(o00); o01=gelu_f(o01); o10=gelu_f(o10); o11=gelu_f(o11); }
            if (v0) *(float2*)&out[(size_t)(base+r0)*Hd + n] = make_float2(o00, o01);
            if (v1) *(float2*)&out[(size_t)(base+r1)*Hd + n] = make_float2(o10, o11);
        }
    }
}

// ---------------- zero counters ----------------
__global__ void k_zero_counts(){
    int i = blockIdx.x*256 + threadIdx.x;
    if (i < Nn){ g_deg[i]=0; g_cnt[i]=0; }
}

// ---------------- bond encoder ----------------
__global__ void k_bond(const float* __restrict__ ea, const float* __restrict__ Wbe,
                       const float* __restrict__ bbe){
    __shared__ float sW[EDd*Hd];
    __shared__ float sattr[16*EDd];
    int tid = threadIdx.x;  // 128
    for (int i=tid;i<EDd*Hd;i+=128) sW[i]=Wbe[i];
    float bias = bbe[tid];
    int e0 = blockIdx.x*16;
    for (int i=tid;i<16*EDd;i+=128){
        int ei = e0 + (i>>4);
        sattr[i] = (ei<Ee) ? ea[ei*EDd + (i&15)] : 0.f;
    }
    __syncthreads();
    #pragma unroll 1
    for (int j=0;j<16;j++){
        int e = e0+j;
        if (e>=Ee) break;
        float acc = bias;
        #pragma unroll
        for (int d=0;d<EDd;d++) acc += sattr[j*EDd+d]*sW[d*Hd+tid];
        g_ee[e*Hd+tid] = acc;
    }
}

// ---------------- CSR build on dst ----------------
__global__ void k_hist(const int* __restrict__ dst){
    int e = blockIdx.x*256 + threadIdx.x;
    if (e < Ee) atomicAdd(&g_deg[dst[e]], 1);
}

__global__ void k_scan1(){
    __shared__ int s[1024];
    int tid = threadIdx.x;
    int i = blockIdx.x*1024 + tid;
    int v = (i<Nn) ? g_deg[i] : 0;
    s[tid] = v; __syncthreads();
    #pragma unroll
    for (int off=1; off<1024; off<<=1){
        int t = (tid>=off) ? s[tid-off] : 0;
        __syncthreads();
        s[tid] += t;
        __syncthreads();
    }
    if (i<Nn) g_offs[i] = s[tid] - v;
    if (tid==1023) g_bsum[blockIdx.x] = s[1023];
}

__global__ void k_scan2(){
    if (threadIdx.x==0){
        int acc = 0;
        for (int b=0;b<NBLK_SCAN;b++){ g_boff[b]=acc; acc+=g_bsum[b]; }
        g_boff[NBLK_SCAN]=acc;
        g_offs[Nn]=acc;
    }
}

__global__ void k_scan3(){
    int i = blockIdx.x*1024 + threadIdx.x;
    if (i<Nn) g_offs[i] += g_boff[blockIdx.x];
}

__global__ void k_fill(const int* __restrict__ dst){
    int e = blockIdx.x*256 + threadIdx.x;
    if (e < Ee){
        int d = dst[e];
        int p = atomicAdd(&g_cnt[d], 1);
        g_csr[g_offs[d]+p] = e;
    }
}

// ---------------- graph boundaries ----------------
__global__ void k_gstart(const int* __restrict__ batch){
    int g = threadIdx.x;
    if (g > Gg) return;
    int lo = 0, hi = Nn;
    while (lo < hi){
        int mid = (lo+hi) >> 1;
        if (batch[mid] < g) lo = mid+1; else hi = mid;
    }
    g_gstart[g] = lo;
}

// ---------------- aggregation ----------------
__global__ void k_agg(const float* __restrict__ xin, const float* __restrict__ em,
                      const int* __restrict__ src, const float* __restrict__ epsp,
                      int l, float* __restrict__ hout){
    int h = threadIdx.x;
    int n = blockIdx.x;
    float ep = 1.0f + epsp[l];
    int beg = g_offs[n], end = g_offs[n+1];
    float a0 = ep * xin[(0*Nn+n)*Hd+h];
    float a1 = ep * xin[(1*Nn+n)*Hd+h];
    float a2 = ep * xin[(2*Nn+n)*Hd+h];
    float a3 = ep * xin[(3*Nn+n)*Hd+h];
    for (int k=beg; k<end; k++){
        int e = g_csr[k];
        int s = src[e];
        float eeh = g_ee[e*Hd+h];
        float m0 = em[0*Ee+e], m1 = em[1*Ee+e], m2 = em[2*Ee+e], m3 = em[3*Ee+e];
        a0 += gelu_f(xin[(0*Nn+s)*Hd+h] + eeh) * m0;
        a1 += gelu_f(xin[(1*Nn+s)*Hd+h] + eeh) * m1;
        a2 += gelu_f(xin[(2*Nn+s)*Hd+h] + eeh) * m2;
        a3 += gelu_f(xin[(3*Nn+s)*Hd+h] + eeh) * m3;
    }
    hout[(0*Nn+n)*Hd+h] = a0;
    hout[(1*Nn+n)*Hd+h] = a1;
    hout[(2*Nn+n)*Hd+h] = a2;
    hout[(3*Nn+n)*Hd+h] = a3;
}

// ---------------- masked mean pool ----------------
__global__ void k_pool(const float* __restrict__ y, const float* __restrict__ nm,
                       float* __restrict__ out){
    __shared__ float snum[512];
    __shared__ float sden[4];
    int f = threadIdx.x & 127;
    int slice = threadIdx.x >> 7;
    int g = blockIdx.x, c = blockIdx.y;
    int beg = g_gstart[g], end = g_gstart[g+1];
    float num = 0.f, den = 0.f;
    for (int n=beg+slice; n<end; n+=4){
        float m = nm[c*Nn+n];
        num += y[(c*Nn+n)*Hd+f]*m;
        den += m;
    }
    snum[threadIdx.x] = num;
    if (f==0) sden[slice] = den;
    __syncthreads();
    if (slice==0){
        float tot = snum[f] + snum[128+f] + snum[256+f] + snum[384+f];
        float d = sden[0]+sden[1]+sden[2]+sden[3] + 1e-7f;
        out[(g*Cc+c)*Hd+f] = tot / d;
    }
}

// ---------------- launch ----------------
extern "C" void kernel_launch(void* const* d_in, const int* in_sizes, int n_in,
                              void* d_out, int out_size){
    const float* x    = (const float*)d_in[0];
    const int*  batch = (const int*)d_in[1];
    const int*  eidx  = (const int*)d_in[2];
    const float* ea   = (const float*)d_in[3];
    const float* nm   = (const float*)d_in[4];
    const float* em   = (const float*)d_in[5];
    const float* Wbe  = (const float*)d_in[6];
    const float* bbe  = (const float*)d_in[7];
    const float* eps  = (const float*)d_in[8];
    const float* W1   = (const float*)d_in[9];
    const float* b1   = (const float*)d_in[10];
    const float* W2   = (const float*)d_in[11];
    const float* b2   = (const float*)d_in[12];
    const float* Wm1  = (const float*)d_in[13];
    const float* bm1  = (const float*)d_in[14];
    const float* Wm2  = (const float*)d_in[15];
    const float* bm2  = (const float*)d_in[16];
    float* out = (float*)d_out;

    const int* src = eidx;
    const int* dst = eidx + Ee;

    float *bufA, *bufB;
    __half* wsp;
    cudaGetSymbolAddress((void**)&bufA, g_bufA);
    cudaGetSymbolAddress((void**)&bufB, g_bufB);
    cudaGetSymbolAddress((void**)&wsp, g_wsp);
    cudaFuncSetAttribute(k_mlp_mma, cudaFuncAttributeMaxDynamicSharedMemorySize, SMEM_MMA);

    // weight prep (mats: 0=W1[0],1=W2[0],2=W1[1],3=W2[1],4=Wm1,5=Wm2)
    k_prepw_all<<<dim3(64, 6), 256>>>(W1, W2, Wm1, Wm2, wsp);

    k_zero_counts<<<(Nn+255)/256, 256>>>();
    k_bond<<<(Ee+15)/16, 128>>>(ea, Wbe, bbe);
    k_hist<<<(Ee+255)/256, 256>>>(dst);
    k_scan1<<<NBLK_SCAN, 1024>>>();
    k_scan2<<<1, 32>>>();
    k_scan3<<<NBLK_SCAN, 1024>>>();
    k_fill<<<(Ee+255)/256, 256>>>(dst);
    k_gstart<<<1, 128>>>(batch);

    const int mlp_grid = (NROWS + 127)/128;

    // layer 0
    k_agg<<<Nn, 128>>>(x, em, src, eps, 0, bufA);
    k_mlp_mma<<<mlp_grid, 256, SMEM_MMA>>>(bufA, bufB,
        wsp + 0*16384, wsp + 1*16384, wsp + 2*16384, wsp + 3*16384, b1, b2, NROWS, 1);
    // layer 1
    k_agg<<<Nn, 128>>>(bufB, em, src, eps, 1, bufA);
    k_mlp_mma<<<mlp_grid, 256, SMEM_MMA>>>(bufA, bufB,
        wsp + 4*16384, wsp + 5*16384, wsp + 6*16384, wsp + 7*16384, b1 + Hd, b2 + Hd, NROWS, 1);
    // final MLP (no outer gelu)
    k_mlp_mma<<<mlp_grid, 256, SMEM_MMA>>>(bufB, bufA,
        wsp + 8*16384, wsp + 9*16384, wsp + 10*16384, wsp + 11*16384, bm1, bm2, NROWS, 0);
    // pool
    k_pool<<<dim3(Gg, Cc), 512>>>(bufA, nm, out);
}

// round 9
// speedup vs baseline: 1.9268x; 1.1637x over previous
#include <cuda_runtime.h>
#include <cuda_fp16.h>
#include <cstdint>
#include <cstring>
#include <math.h>

#define Nn 50000
#define Ee 200000
#define Hd 128
#define Cc 4
#define Gg 64
#define EDd 16
#define NROWS (Cc*Nn)   // 200000
#define NBLK_SCAN ((Nn + 1023)/1024)   // 49

// ---------------- scratch (device globals; no allocation allowed) ----------------
__device__ __align__(128) __half g_eeh[Ee*Hd];        // bond-encoded edge features (fp16)
__device__ __align__(128) __half g_xh[NROWS*Hd];      // input x in fp16
__device__ __align__(128) __half g_bufA[NROWS*Hd];
__device__ __align__(128) __half g_bufB[NROWS*Hd];
__device__ int g_deg[Nn];
__device__ int g_offs[Nn+1];
__device__ int g_cnt[Nn];
__device__ int g_csr[Ee];
__device__ int g_gstart[Gg+1];
__device__ int g_bsum[NBLK_SCAN];
__device__ int g_boff[NBLK_SCAN+1];
// pre-split weights: 6 matrices x {hi,lo} x 16384 fp16, row-major [k][n]
__device__ __align__(128) __half g_wsp[6*2*16384];

__device__ __forceinline__ float gelu_f(float v){
    return 0.5f*v*(1.0f+erff(v*0.7071067811865475f));
}

__device__ __forceinline__ uint32_t smem_u32(const void* p){
    uint32_t a;
    asm("{ .reg .u64 t; cvta.to.shared.u64 t, %1; cvt.u32.u64 %0, t; }" : "=r"(a) : "l"(p));
    return a;
}
__device__ __forceinline__ void ldsm_x4(uint32_t& r0, uint32_t& r1, uint32_t& r2, uint32_t& r3, uint32_t addr){
    asm volatile("ldmatrix.sync.aligned.m8n8.x4.shared.b16 {%0,%1,%2,%3}, [%4];"
        : "=r"(r0), "=r"(r1), "=r"(r2), "=r"(r3) : "r"(addr));
}
__device__ __forceinline__ void ldsm_x2t(uint32_t& r0, uint32_t& r1, uint32_t addr){
    asm volatile("ldmatrix.sync.aligned.m8n8.x2.trans.shared.b16 {%0,%1}, [%2];"
        : "=r"(r0), "=r"(r1) : "r"(addr));
}
__device__ __forceinline__ void mma_fp16(float* c, const uint32_t* a, uint32_t b0, uint32_t b1){
    asm volatile("mma.sync.aligned.m16n8k16.row.col.f32.f16.f16.f32 "
        "{%0,%1,%2,%3},{%4,%5,%6,%7},{%8,%9},{%0,%1,%2,%3};"
        : "+f"(c[0]), "+f"(c[1]), "+f"(c[2]), "+f"(c[3])
        : "r"(a[0]), "r"(a[1]), "r"(a[2]), "r"(a[3]), "r"(b0), "r"(b1));
}
__device__ __forceinline__ uint32_t pack_h2(float a, float b){
    __half2 t = __floats2half2_rn(a, b);
    uint32_t u; memcpy(&u, &t, 4); return u;
}

// ---------------- weight prep: split fp32 W[k][n] -> fp16 hi/lo (all 6 mats) ----------------
__global__ void k_prepw_all(const float* __restrict__ W1, const float* __restrict__ W2,
                            const float* __restrict__ Wm1, const float* __restrict__ Wm2,
                            __half* __restrict__ outw){
    int mat = blockIdx.y;
    const float* src;
    switch (mat){
        case 0: src = W1;          break;
        case 1: src = W2;          break;
        case 2: src = W1 + 16384;  break;
        case 3: src = W2 + 16384;  break;
        case 4: src = Wm1;         break;
        default: src = Wm2;        break;
    }
    int idx = blockIdx.x*256 + threadIdx.x;
    if (idx >= 16384) return;
    float w = src[idx];
    __half h = __float2half_rn(w);
    __half l = __float2half_rn(w - __half2float(h));
    outw[(mat*2+0)*16384 + idx] = h;
    outw[(mat*2+1)*16384 + idx] = l;
}

// ---------------- x fp32 -> fp16 ----------------
__global__ void k_x2h(const float* __restrict__ x, __half* __restrict__ xh){
    int i = blockIdx.x*256 + threadIdx.x;
    if (i < NROWS*Hd/4){
        float4 v = ((const float4*)x)[i];
        uint2 o; o.x = pack_h2(v.x, v.y); o.y = pack_h2(v.z, v.w);
        ((uint2*)xh)[i] = o;
    }
}

// ---------------- mma.sync fused MLP (fp16 in/out, 256-row tiles, 512 thr) ----------------
// smem (halves): A [256][LDA], WAH/WAL/WBH/WBL [128][LDA]
#define LDA 136
#define SM_A   0
#define SM_WAH (256*LDA)
#define SM_WAL (256*LDA + 128*LDA)
#define SM_WBH (256*LDA + 2*128*LDA)
#define SM_WBL (256*LDA + 3*128*LDA)
#define SMEM_MMA ((256*LDA + 4*128*LDA)*2)   // 208896 bytes

// warp tile: 32 rows x 64 cols; acc[mt][nt][4]
__device__ __forceinline__ void gemm_2t(uint32_t sb, int w_h, int w_l,
                                        float acc[2][8][4], int m0, int wn, int lane){
    uint32_t aaddr  = sb + 2u*((uint32_t)(SM_A + (m0 + (lane&15))*LDA + (lane>>4)*8));
    uint32_t baddrh = sb + 2u*((uint32_t)(w_h + (lane&15)*LDA + wn*64));
    uint32_t baddrl = sb + 2u*((uint32_t)(w_l + (lane&15)*LDA + wn*64));
    #pragma unroll
    for (int kb = 0; kb < 8; kb++){
        uint32_t a0[4], a1[4];
        ldsm_x4(a0[0], a0[1], a0[2], a0[3], aaddr + kb*32);
        ldsm_x4(a1[0], a1[1], a1[2], a1[3], aaddr + 16*LDA*2 + kb*32);
        uint32_t bstep = (uint32_t)kb*(16*LDA*2);
        #pragma unroll
        for (int nt = 0; nt < 8; nt++){
            uint32_t bh0, bh1, bl0, bl1;
            ldsm_x2t(bh0, bh1, baddrh + bstep + nt*16);
            ldsm_x2t(bl0, bl1, baddrl + bstep + nt*16);
            mma_fp16(acc[0][nt], a0, bh0, bh1);
            mma_fp16(acc[0][nt], a0, bl0, bl1);
            mma_fp16(acc[1][nt], a1, bh0, bh1);
            mma_fp16(acc[1][nt], a1, bl0, bl1);
        }
    }
}

__global__ void __launch_bounds__(512, 1)
k_mlp_mma(const __half* __restrict__ in, __half* __restrict__ out,
          const __half* __restrict__ wa_hi, const __half* __restrict__ wa_lo,
          const __half* __restrict__ wb_hi, const __half* __restrict__ wb_lo,
          const float* __restrict__ ba, const float* __restrict__ bb,
          int rows, int outer_gelu){
    extern __shared__ __half sm[];
    const uint32_t sb = smem_u32(sm);
    const int tid = threadIdx.x;
    const int base = blockIdx.x*256;

    // weights gmem -> padded smem (uint4 = 8 halves): 2048 uint4 each, 4 iters
    {
        const uint4* s0 = (const uint4*)wa_hi; const uint4* s1 = (const uint4*)wa_lo;
        const uint4* s2 = (const uint4*)wb_hi; const uint4* s3 = (const uint4*)wb_lo;
        #pragma unroll
        for (int i = tid; i < 2048; i += 512){
            int row = i >> 4, c8 = (i & 15)*8;
            int d = row*LDA + c8;
            *(uint4*)&sm[SM_WAH + d] = s0[i];
            *(uint4*)&sm[SM_WAL + d] = s1[i];
            *(uint4*)&sm[SM_WBH + d] = s2[i];
            *(uint4*)&sm[SM_WBL + d] = s3[i];
        }
    }
    // A tile: raw fp16 copy, 256 rows x 16 uint4
    {
        #pragma unroll
        for (int i = tid; i < 4096; i += 512){
            int row = i >> 4, c8 = (i & 15)*8;
            uint4 v = make_uint4(0u,0u,0u,0u);
            if (base + row < rows) v = *(const uint4*)&in[(size_t)(base+row)*Hd + c8];
            *(uint4*)&sm[SM_A + row*LDA + c8] = v;
        }
    }
    __syncthreads();

    const int w = tid >> 5, lane = tid & 31;
    const int wm = w & 7, wn = w >> 3;
    const int m0 = wm*32;
    const int grp = lane >> 2, quad = lane & 3;
    float acc[2][8][4];

    // ---- GEMM1 ----
    #pragma unroll
    for (int mt = 0; mt < 2; mt++)
        #pragma unroll
        for (int nt = 0; nt < 8; nt++){ acc[mt][nt][0]=0.f; acc[mt][nt][1]=0.f; acc[mt][nt][2]=0.f; acc[mt][nt][3]=0.f; }
    gemm_2t(sb, SM_WAH, SM_WAL, acc, m0, wn, lane);
    __syncthreads();   // all A reads done before overwrite

    // epilogue 1: +bias, gelu, back to A as fp16
    #pragma unroll
    for (int mt = 0; mt < 2; mt++){
        int r0 = m0 + mt*16 + grp, r1 = r0 + 8;
        #pragma unroll
        for (int nt = 0; nt < 8; nt++){
            int n = wn*64 + nt*8 + quad*2;
            float b0 = ba[n], b1 = ba[n+1];
            float v00 = gelu_f(acc[mt][nt][0] + b0), v01 = gelu_f(acc[mt][nt][1] + b1);
            float v10 = gelu_f(acc[mt][nt][2] + b0), v11 = gelu_f(acc[mt][nt][3] + b1);
            *(uint32_t*)&sm[SM_A + r0*LDA + n] = pack_h2(v00, v01);
            *(uint32_t*)&sm[SM_A + r1*LDA + n] = pack_h2(v10, v11);
        }
    }
    __syncthreads();

    // ---- GEMM2 ----
    #pragma unroll
    for (int mt = 0; mt < 2; mt++)
        #pragma unroll
        for (int nt = 0; nt < 8; nt++){ acc[mt][nt][0]=0.f; acc[mt][nt][1]=0.f; acc[mt][nt][2]=0.f; acc[mt][nt][3]=0.f; }
    gemm_2t(sb, SM_WBH, SM_WBL, acc, m0, wn, lane);

    // epilogue 2: +bias, optional gelu, store fp16
    #pragma unroll
    for (int mt = 0; mt < 2; mt++){
        int r0 = m0 + mt*16 + grp, r1 = r0 + 8;
        bool v0 = (base + r0) < rows, v1 = (base + r1) < rows;
        #pragma unroll
        for (int nt = 0; nt < 8; nt++){
            int n = wn*64 + nt*8 + quad*2;
            float b0 = bb[n], b1 = bb[n+1];
            float o00 = acc[mt][nt][0] + b0, o01 = acc[mt][nt][1] + b1;
            float o10 = acc[mt][nt][2] + b0, o11 = acc[mt][nt][3] + b1;
            if (outer_gelu){ o00=gelu_f(o00); o01=gelu_f(o01); o10=gelu_f(o10); o11=gelu_f(o11); }
            if (v0) *(uint32_t*)&out[(size_t)(base+r0)*Hd + n] = pack_h2(o00, o01);
            if (v1) *(uint32_t*)&out[(size_t)(base+r1)*Hd + n] = pack_h2(o10, o11);
        }
    }
}

// ---------------- zero counters ----------------
__global__ void k_zero_counts(){
    int i = blockIdx.x*256 + threadIdx.x;
    if (i < Nn){ g_deg[i]=0; g_cnt[i]=0; }
}

// ---------------- bond encoder (fp16 out) ----------------
__global__ void k_bond(const float* __restrict__ ea, const float* __restrict__ Wbe,
                       const float* __restrict__ bbe){
    __shared__ float sW[EDd*Hd];
    __shared__ float sattr[16*EDd];
    int tid = threadIdx.x;  // 128
    for (int i=tid;i<EDd*Hd;i+=128) sW[i]=Wbe[i];
    float bias = bbe[tid];
    int e0 = blockIdx.x*16;
    for (int i=tid;i<16*EDd;i+=128){
        int ei = e0 + (i>>4);
        sattr[i] = (ei<Ee) ? ea[ei*EDd + (i&15)] : 0.f;
    }
    __syncthreads();
    #pragma unroll 1
    for (int j=0;j<16;j++){
        int e = e0+j;
        if (e>=Ee) break;
        float acc = bias;
        #pragma unroll
        for (int d=0;d<EDd;d++) acc += sattr[j*EDd+d]*sW[d*Hd+tid];
        g_eeh[e*Hd+tid] = __float2half_rn(acc);
    }
}

// ---------------- CSR build on dst ----------------
__global__ void k_hist(const int* __restrict__ dst){
    int e = blockIdx.x*256 + threadIdx.x;
    if (e < Ee) atomicAdd(&g_deg[dst[e]], 1);
}

__global__ void k_scan1(){
    __shared__ int s[1024];
    int tid = threadIdx.x;
    int i = blockIdx.x*1024 + tid;
    int v = (i<Nn) ? g_deg[i] : 0;
    s[tid] = v; __syncthreads();
    #pragma unroll
    for (int off=1; off<1024; off<<=1){
        int t = (tid>=off) ? s[tid-off] : 0;
        __syncthreads();
        s[tid] += t;
        __syncthreads();
    }
    if (i<Nn) g_offs[i] = s[tid] - v;
    if (tid==1023) g_bsum[blockIdx.x] = s[1023];
}

__global__ void k_scan2(){
    if (threadIdx.x==0){
        int acc = 0;
        for (int b=0;b<NBLK_SCAN;b++){ g_boff[b]=acc; acc+=g_bsum[b]; }
        g_boff[NBLK_SCAN]=acc;
        g_offs[Nn]=acc;
    }
}

__global__ void k_scan3(){
    int i = blockIdx.x*1024 + threadIdx.x;
    if (i<Nn) g_offs[i] += g_boff[blockIdx.x];
}

__global__ void k_fill(const int* __restrict__ dst){
    int e = blockIdx.x*256 + threadIdx.x;
    if (e < Ee){
        int d = dst[e];
        int p = atomicAdd(&g_cnt[d], 1);
        g_csr[g_offs[d]+p] = e;
    }
}

// ---------------- graph boundaries ----------------
__global__ void k_gstart(const int* __restrict__ batch){
    int g = threadIdx.x;
    if (g > Gg) return;
    int lo = 0, hi = Nn;
    while (lo < hi){
        int mid = (lo+hi) >> 1;
        if (batch[mid] < g) lo = mid+1; else hi = mid;
    }
    g_gstart[g] = lo;
}

// ---------------- aggregation (fp16 in/out) ----------------
__global__ void k_agg(const __half* __restrict__ xin, const float* __restrict__ em,
                      const int* __restrict__ src, const float* __restrict__ epsp,
                      int l, __half* __restrict__ hout){
    int h = threadIdx.x;
    int n = blockIdx.x;
    float ep = 1.0f + epsp[l];
    int beg = g_offs[n], end = g_offs[n+1];
    float a0 = ep * __half2float(xin[(size_t)(0*Nn+n)*Hd+h]);
    float a1 = ep * __half2float(xin[(size_t)(1*Nn+n)*Hd+h]);
    float a2 = ep * __half2float(xin[(size_t)(2*Nn+n)*Hd+h]);
    float a3 = ep * __half2float(xin[(size_t)(3*Nn+n)*Hd+h]);
    for (int k=beg; k<end; k++){
        int e = g_csr[k];
        int s = src[e];
        float eeh = __half2float(g_eeh[e*Hd+h]);
        float m0 = em[0*Ee+e], m1 = em[1*Ee+e], m2 = em[2*Ee+e], m3 = em[3*Ee+e];
        a0 += gelu_f(__half2float(xin[(size_t)(0*Nn+s)*Hd+h]) + eeh) * m0;
        a1 += gelu_f(__half2float(xin[(size_t)(1*Nn+s)*Hd+h]) + eeh) * m1;
        a2 += gelu_f(__half2float(xin[(size_t)(2*Nn+s)*Hd+h]) + eeh) * m2;
        a3 += gelu_f(__half2float(xin[(size_t)(3*Nn+s)*Hd+h]) + eeh) * m3;
    }
    hout[(size_t)(0*Nn+n)*Hd+h] = __float2half_rn(a0);
    hout[(size_t)(1*Nn+n)*Hd+h] = __float2half_rn(a1);
    hout[(size_t)(2*Nn+n)*Hd+h] = __float2half_rn(a2);
    hout[(size_t)(3*Nn+n)*Hd+h] = __float2half_rn(a3);
}

// ---------------- masked mean pool (fp16 y) ----------------
__global__ void k_pool(const __half* __restrict__ y, const float* __restrict__ nm,
                       float* __restrict__ out){
    __shared__ float snum[512];
    __shared__ float sden[4];
    int f = threadIdx.x & 127;
    int slice = threadIdx.x >> 7;
    int g = blockIdx.x, c = blockIdx.y;
    int beg = g_gstart[g], end = g_gstart[g+1];
    float num = 0.f, den = 0.f;
    for (int n=beg+slice; n<end; n+=4){
        float m = nm[c*Nn+n];
        num += __half2float(y[(size_t)(c*Nn+n)*Hd+f])*m;
        den += m;
    }
    snum[threadIdx.x] = num;
    if (f==0) sden[slice] = den;
    __syncthreads();
    if (slice==0){
        float tot = snum[f] + snum[128+f] + snum[256+f] + snum[384+f];
        float d = sden[0]+sden[1]+sden[2]+sden[3] + 1e-7f;
        out[(g*Cc+c)*Hd+f] = tot / d;
    }
}

// ---------------- launch ----------------
extern "C" void kernel_launch(void* const* d_in, const int* in_sizes, int n_in,
                              void* d_out, int out_size){
    const float* x    = (const float*)d_in[0];
    const int*  batch = (const int*)d_in[1];
    const int*  eidx  = (const int*)d_in[2];
    const float* ea   = (const float*)d_in[3];
    const float* nm   = (const float*)d_in[4];
    const float* em   = (const float*)d_in[5];
    const float* Wbe  = (const float*)d_in[6];
    const float* bbe  = (const float*)d_in[7];
    const float* eps  = (const float*)d_in[8];
    const float* W1   = (const float*)d_in[9];
    const float* b1   = (const float*)d_in[10];
    const float* W2   = (const float*)d_in[11];
    const float* b2   = (const float*)d_in[12];
    const float* Wm1  = (const float*)d_in[13];
    const float* bm1  = (const float*)d_in[14];
    const float* Wm2  = (const float*)d_in[15];
    const float* bm2  = (const float*)d_in[16];
    float* out = (float*)d_out;

    const int* src = eidx;
    const int* dst = eidx + Ee;

    __half *xh, *bufA, *bufB, *wsp;
    cudaGetSymbolAddress((void**)&xh,   g_xh);
    cudaGetSymbolAddress((void**)&bufA, g_bufA);
    cudaGetSymbolAddress((void**)&bufB, g_bufB);
    cudaGetSymbolAddress((void**)&wsp,  g_wsp);
    cudaFuncSetAttribute(k_mlp_mma, cudaFuncAttributeMaxDynamicSharedMemorySize, SMEM_MMA);

    // prep
    k_prepw_all<<<dim3(64, 6), 256>>>(W1, W2, Wm1, Wm2, wsp);
    k_x2h<<<(NROWS*Hd/4 + 255)/256, 256>>>(x, xh);
    k_zero_counts<<<(Nn+255)/256, 256>>>();
    k_bond<<<(Ee+15)/16, 128>>>(ea, Wbe, bbe);
    k_hist<<<(Ee+255)/256, 256>>>(dst);
    k_scan1<<<NBLK_SCAN, 1024>>>();
    k_scan2<<<1, 32>>>();
    k_scan3<<<NBLK_SCAN, 1024>>>();
    k_fill<<<(Ee+255)/256, 256>>>(dst);
    k_gstart<<<1, 128>>>(batch);

    const int mlp_grid = (NROWS + 255)/256;

    // layer 0
    k_agg<<<Nn, 128>>>(xh, em, src, eps, 0, bufA);
    k_mlp_mma<<<mlp_grid, 512, SMEM_MMA>>>(bufA, bufB,
        wsp + 0*16384, wsp + 1*16384, wsp + 2*16384, wsp + 3*16384, b1, b2, NROWS, 1);
    // layer 1
    k_agg<<<Nn, 128>>>(bufB, em, src, eps, 1, bufA);
    k_mlp_mma<<<mlp_grid, 512, SMEM_MMA>>>(bufA, bufB,
        wsp + 4*16384, wsp + 5*16384, wsp + 6*16384, wsp + 7*16384, b1 + Hd, b2 + Hd, NROWS, 1);
    // final MLP (no outer gelu)
    k_mlp_mma<<<mlp_grid, 512, SMEM_MMA>>>(bufB, bufA,
        wsp + 8*16384, wsp + 9*16384, wsp + 10*16384, wsp + 11*16384, bm1, bm2, NROWS, 0);
    // pool
    k_pool<<<dim3(Gg, Cc), 512>>>(bufA, nm, out);
}

// round 10
// speedup vs baseline: 1.9898x; 1.0327x over previous
#include <cuda_runtime.h>
#include <cuda_fp16.h>
#include <cstdint>
#include <cstring>
#include <math.h>

#define Nn 50000
#define Ee 200000
#define Hd 128
#define Cc 4
#define Gg 64
#define EDd 16
#define NROWS (Cc*Nn)   // 200000
#define NBLK_SCAN ((Nn + 1023)/1024)   // 49

// ---------------- scratch (device globals; no allocation allowed) ----------------
__device__ __align__(128) __half g_eeh[Ee*Hd];        // bond-encoded edge features (fp16)
__device__ __align__(128) __half g_xh[NROWS*Hd];      // input x in fp16
__device__ __align__(128) __half g_bufA[NROWS*Hd];
__device__ __align__(128) __half g_bufB[NROWS*Hd];
__device__ int g_deg[Nn];
__device__ int g_offs[Nn+1];
__device__ int g_cnt[Nn];
__device__ int g_csr[Ee];
__device__ int g_gstart[Gg+1];
__device__ int g_bsum[NBLK_SCAN];
__device__ int g_boff[NBLK_SCAN+1];
// pre-split weights: 6 matrices x {hi,lo} x 16384 fp16, row-major [k][n]
__device__ __align__(128) __half g_wsp[6*2*16384];

__device__ __forceinline__ float gelu_f(float v){
    return 0.5f*v*(1.0f+erff(v*0.7071067811865475f));
}

__device__ __forceinline__ uint32_t smem_u32(const void* p){
    uint32_t a;
    asm("{ .reg .u64 t; cvta.to.shared.u64 t, %1; cvt.u32.u64 %0, t; }" : "=r"(a) : "l"(p));
    return a;
}
__device__ __forceinline__ void ldsm_x4(uint32_t& r0, uint32_t& r1, uint32_t& r2, uint32_t& r3, uint32_t addr){
    asm volatile("ldmatrix.sync.aligned.m8n8.x4.shared.b16 {%0,%1,%2,%3}, [%4];"
        : "=r"(r0), "=r"(r1), "=r"(r2), "=r"(r3) : "r"(addr));
}
__device__ __forceinline__ void ldsm_x4t(uint32_t* r, uint32_t addr){
    asm volatile("ldmatrix.sync.aligned.m8n8.x4.trans.shared.b16 {%0,%1,%2,%3}, [%4];"
        : "=r"(r[0]), "=r"(r[1]), "=r"(r[2]), "=r"(r[3]) : "r"(addr));
}
__device__ __forceinline__ void mma_fp16(float* c, const uint32_t* a, uint32_t b0, uint32_t b1){
    asm volatile("mma.sync.aligned.m16n8k16.row.col.f32.f16.f16.f32 "
        "{%0,%1,%2,%3},{%4,%5,%6,%7},{%8,%9},{%0,%1,%2,%3};"
        : "+f"(c[0]), "+f"(c[1]), "+f"(c[2]), "+f"(c[3])
        : "r"(a[0]), "r"(a[1]), "r"(a[2]), "r"(a[3]), "r"(b0), "r"(b1));
}
__device__ __forceinline__ uint32_t pack_h2(float a, float b){
    __half2 t = __floats2half2_rn(a, b);
    uint32_t u; memcpy(&u, &t, 4); return u;
}

// ---------------- weight prep: split fp32 W[k][n] -> fp16 hi/lo (all 6 mats) ----------------
__global__ void k_prepw_all(const float* __restrict__ W1, const float* __restrict__ W2,
                            const float* __restrict__ Wm1, const float* __restrict__ Wm2,
                            __half* __restrict__ outw){
    int mat = blockIdx.y;
    const float* src;
    switch (mat){
        case 0: src = W1;          break;
        case 1: src = W2;          break;
        case 2: src = W1 + 16384;  break;
        case 3: src = W2 + 16384;  break;
        case 4: src = Wm1;         break;
        default: src = Wm2;        break;
    }
    int idx = blockIdx.x*256 + threadIdx.x;
    if (idx >= 16384) return;
    float w = src[idx];
    __half h = __float2half_rn(w);
    __half l = __float2half_rn(w - __half2float(h));
    outw[(mat*2+0)*16384 + idx] = h;
    outw[(mat*2+1)*16384 + idx] = l;
}

// ---------------- x fp32 -> fp16 ----------------
__global__ void k_x2h(const float* __restrict__ x, __half* __restrict__ xh){
    int i = blockIdx.x*256 + threadIdx.x;
    if (i < NROWS*Hd/4){
        float4 v = ((const float4*)x)[i];
        uint2 o; o.x = pack_h2(v.x, v.y); o.y = pack_h2(v.z, v.w);
        ((uint2*)xh)[i] = o;
    }
}

// ---------------- bond encoder via mma: ee = edge_attr[E,16] @ W_be[16,128] + b_be ----------------
// 512 threads, 256-edge tile; K=16 (single k-block), W hi/lo split in-kernel.
#define LDB_A 24     // padded A row (halves), 48B rows (16B multiple)
__global__ void __launch_bounds__(512, 2)
k_bond_mma(const float* __restrict__ ea, const float* __restrict__ Wbe,
           const float* __restrict__ bbe){
    __shared__ __half sA[256*LDB_A];
    __shared__ __half sWh[16*136];
    __shared__ __half sWl[16*136];
    const int tid = threadIdx.x;
    const int base = blockIdx.x*256;

    // W split: 2048 elems
    #pragma unroll
    for (int i = tid; i < 2048; i += 512){
        int k = i >> 7, n = i & 127;
        float w = Wbe[i];
        __half h = __float2half_rn(w);
        sWh[k*136 + n] = h;
        sWl[k*136 + n] = __float2half_rn(w - __half2float(h));
    }
    // A: 256 edges x 16 attrs (fp32 -> fp16); 1024 float4
    #pragma unroll
    for (int i = tid; i < 1024; i += 512){
        int row = i >> 2, c4 = (i & 3)*4;
        float4 v = make_float4(0.f,0.f,0.f,0.f);
        if (base + row < Ee) v = *(const float4*)&ea[(size_t)(base+row)*EDd + c4];
        uint2 o; o.x = pack_h2(v.x, v.y); o.y = pack_h2(v.z, v.w);
        *(uint2*)&sA[row*LDB_A + c4] = o;
    }
    __syncthreads();

    const uint32_t sbA = smem_u32(sA), sbWh = smem_u32(sWh), sbWl = smem_u32(sWl);
    const int w = tid >> 5, lane = tid & 31;
    const int wm = w & 7, wn = w >> 3;
    const int m0 = wm*32;
    const int grp = lane >> 2, quad = lane & 3;

    // A fragments (k=16): one x4 per mt
    uint32_t a0[4], a1[4];
    {
        uint32_t aaddr = sbA + 2u*((uint32_t)((m0 + (lane&15))*LDB_A + (lane>>4)*8));
        ldsm_x4(a0[0], a0[1], a0[2], a0[3], aaddr);
        ldsm_x4(a1[0], a1[1], a1[2], a1[3], aaddr + 16*LDB_A*2);
    }
    float acc[2][8][4];
    #pragma unroll
    for (int mt = 0; mt < 2; mt++)
        #pragma unroll
        for (int nt = 0; nt < 8; nt++){ acc[mt][nt][0]=0.f; acc[mt][nt][1]=0.f; acc[mt][nt][2]=0.f; acc[mt][nt][3]=0.f; }

    {
        uint32_t bh_base = sbWh + 2u*((uint32_t)((lane&15)*136 + wn*64 + (lane>>4)*8));
        uint32_t bl_base = sbWl + 2u*((uint32_t)((lane&15)*136 + wn*64 + (lane>>4)*8));
        #pragma unroll
        for (int ntp = 0; ntp < 4; ntp++){
            uint32_t bh[4], bl[4];
            ldsm_x4t(bh, bh_base + ntp*32);
            ldsm_x4t(bl, bl_base + ntp*32);
            mma_fp16(acc[0][2*ntp],   a0, bh[0], bh[1]);
            mma_fp16(acc[0][2*ntp],   a0, bl[0], bl[1]);
            mma_fp16(acc[1][2*ntp],   a1, bh[0], bh[1]);
            mma_fp16(acc[1][2*ntp],   a1, bl[0], bl[1]);
            mma_fp16(acc[0][2*ntp+1], a0, bh[2], bh[3]);
            mma_fp16(acc[0][2*ntp+1], a0, bl[2], bl[3]);
            mma_fp16(acc[1][2*ntp+1], a1, bh[2], bh[3]);
            mma_fp16(acc[1][2*ntp+1], a1, bl[2], bl[3]);
        }
    }
    // epilogue: +bias, store fp16
    #pragma unroll
    for (int mt = 0; mt < 2; mt++){
        int r0 = m0 + mt*16 + grp, r1 = r0 + 8;
        bool v0 = (base + r0) < Ee, v1 = (base + r1) < Ee;
        #pragma unroll
        for (int nt = 0; nt < 8; nt++){
            int n = wn*64 + nt*8 + quad*2;
            float b0 = bbe[n], b1 = bbe[n+1];
            if (v0) *(uint32_t*)&g_eeh[(size_t)(base+r0)*Hd + n] = pack_h2(acc[mt][nt][0]+b0, acc[mt][nt][1]+b1);
            if (v1) *(uint32_t*)&g_eeh[(size_t)(base+r1)*Hd + n] = pack_h2(acc[mt][nt][2]+b0, acc[mt][nt][3]+b1);
        }
    }
}

// ---------------- mma.sync fused MLP (fp16 in/out, 256-row tiles, 512 thr) ----------------
#define LDA 136
#define SM_A   0
#define SM_WAH (256*LDA)
#define SM_WAL (256*LDA + 128*LDA)
#define SM_WBH (256*LDA + 2*128*LDA)
#define SM_WBL (256*LDA + 3*128*LDA)
#define SMEM_MMA ((256*LDA + 4*128*LDA)*2)   // 208896 bytes

// warp tile: 32 rows x 64 cols; B via x4.trans (2 n-tiles per ldsm)
__device__ __forceinline__ void gemm_2t(uint32_t sb, int w_h, int w_l,
                                        float acc[2][8][4], int m0, int wn, int lane){
    uint32_t aaddr  = sb + 2u*((uint32_t)(SM_A + (m0 + (lane&15))*LDA + (lane>>4)*8));
    uint32_t baddrh = sb + 2u*((uint32_t)(w_h + (lane&15)*LDA + wn*64 + (lane>>4)*8));
    uint32_t baddrl = sb + 2u*((uint32_t)(w_l + (lane&15)*LDA + wn*64 + (lane>>4)*8));
    #pragma unroll
    for (int kb = 0; kb < 8; kb++){
        uint32_t a0[4], a1[4];
        ldsm_x4(a0[0], a0[1], a0[2], a0[3], aaddr + kb*32);
        ldsm_x4(a1[0], a1[1], a1[2], a1[3], aaddr + 16*LDA*2 + kb*32);
        uint32_t bstep = (uint32_t)kb*(16*LDA*2);
        #pragma unroll
        for (int ntp = 0; ntp < 4; ntp++){
            uint32_t bh[4], bl[4];
            ldsm_x4t(bh, baddrh + bstep + ntp*32);
            ldsm_x4t(bl, baddrl + bstep + ntp*32);
            mma_fp16(acc[0][2*ntp],   a0, bh[0], bh[1]);
            mma_fp16(acc[0][2*ntp],   a0, bl[0], bl[1]);
            mma_fp16(acc[1][2*ntp],   a1, bh[0], bh[1]);
            mma_fp16(acc[1][2*ntp],   a1, bl[0], bl[1]);
            mma_fp16(acc[0][2*ntp+1], a0, bh[2], bh[3]);
            mma_fp16(acc[0][2*ntp+1], a0, bl[2], bl[3]);
            mma_fp16(acc[1][2*ntp+1], a1, bh[2], bh[3]);
            mma_fp16(acc[1][2*ntp+1], a1, bl[2], bl[3]);
        }
    }
}

__global__ void __launch_bounds__(512, 1)
k_mlp_mma(const __half* __restrict__ in, __half* __restrict__ out,
          const __half* __restrict__ wa_hi, const __half* __restrict__ wa_lo,
          const __half* __restrict__ wb_hi, const __half* __restrict__ wb_lo,
          const float* __restrict__ ba, const float* __restrict__ bb,
          int rows, int outer_gelu){
    extern __shared__ __half sm[];
    const uint32_t sb = smem_u32(sm);
    const int tid = threadIdx.x;
    const int base = blockIdx.x*256;

    {   // weights gmem -> padded smem (uint4 = 8 halves)
        const uint4* s0 = (const uint4*)wa_hi; const uint4* s1 = (const uint4*)wa_lo;
        const uint4* s2 = (const uint4*)wb_hi; const uint4* s3 = (const uint4*)wb_lo;
        #pragma unroll
        for (int i = tid; i < 2048; i += 512){
            int row = i >> 4, c8 = (i & 15)*8;
            int d = row*LDA + c8;
            *(uint4*)&sm[SM_WAH + d] = s0[i];
            *(uint4*)&sm[SM_WAL + d] = s1[i];
            *(uint4*)&sm[SM_WBH + d] = s2[i];
            *(uint4*)&sm[SM_WBL + d] = s3[i];
        }
    }
    {   // A tile: raw fp16 copy
        #pragma unroll
        for (int i = tid; i < 4096; i += 512){
            int row = i >> 4, c8 = (i & 15)*8;
            uint4 v = make_uint4(0u,0u,0u,0u);
            if (base + row < rows) v = *(const uint4*)&in[(size_t)(base+row)*Hd + c8];
            *(uint4*)&sm[SM_A + row*LDA + c8] = v;
        }
    }
    __syncthreads();

    const int w = tid >> 5, lane = tid & 31;
    const int wm = w & 7, wn = w >> 3;
    const int m0 = wm*32;
    const int grp = lane >> 2, quad = lane & 3;
    float acc[2][8][4];

    // ---- GEMM1 ----
    #pragma unroll
    for (int mt = 0; mt < 2; mt++)
        #pragma unroll
        for (int nt = 0; nt < 8; nt++){ acc[mt][nt][0]=0.f; acc[mt][nt][1]=0.f; acc[mt][nt][2]=0.f; acc[mt][nt][3]=0.f; }
    gemm_2t(sb, SM_WAH, SM_WAL, acc, m0, wn, lane);
    __syncthreads();

    // epilogue 1: +bias, gelu, back to A as fp16
    #pragma unroll
    for (int mt = 0; mt < 2; mt++){
        int r0 = m0 + mt*16 + grp, r1 = r0 + 8;
        #pragma unroll
        for (int nt = 0; nt < 8; nt++){
            int n = wn*64 + nt*8 + quad*2;
            float b0 = ba[n], b1 = ba[n+1];
            float v00 = gelu_f(acc[mt][nt][0] + b0), v01 = gelu_f(acc[mt][nt][1] + b1);
            float v10 = gelu_f(acc[mt][nt][2] + b0), v11 = gelu_f(acc[mt][nt][3] + b1);
            *(uint32_t*)&sm[SM_A + r0*LDA + n] = pack_h2(v00, v01);
            *(uint32_t*)&sm[SM_A + r1*LDA + n] = pack_h2(v10, v11);
        }
    }
    __syncthreads();

    // ---- GEMM2 ----
    #pragma unroll
    for (int mt = 0; mt < 2; mt++)
        #pragma unroll
        for (int nt = 0; nt < 8; nt++){ acc[mt][nt][0]=0.f; acc[mt][nt][1]=0.f; acc[mt][nt][2]=0.f; acc[mt][nt][3]=0.f; }
    gemm_2t(sb, SM_WBH, SM_WBL, acc, m0, wn, lane);

    // epilogue 2: +bias, optional gelu, store fp16
    #pragma unroll
    for (int mt = 0; mt < 2; mt++){
        int r0 = m0 + mt*16 + grp, r1 = r0 + 8;
        bool v0 = (base + r0) < rows, v1 = (base + r1) < rows;
        #pragma unroll
        for (int nt = 0; nt < 8; nt++){
            int n = wn*64 + nt*8 + quad*2;
            float b0 = bb[n], b1 = bb[n+1];
            float o00 = acc[mt][nt][0] + b0, o01 = acc[mt][nt][1] + b1;
            float o10 = acc[mt][nt][2] + b0, o11 = acc[mt][nt][3] + b1;
            if (outer_gelu){ o00=gelu_f(o00); o01=gelu_f(o01); o10=gelu_f(o10); o11=gelu_f(o11); }
            if (v0) *(uint32_t*)&out[(size_t)(base+r0)*Hd + n] = pack_h2(o00, o01);
            if (v1) *(uint32_t*)&out[(size_t)(base+r1)*Hd + n] = pack_h2(o10, o11);
        }
    }
}

// ---------------- zero counters ----------------
__global__ void k_zero_counts(){
    int i = blockIdx.x*256 + threadIdx.x;
    if (i < Nn){ g_deg[i]=0; g_cnt[i]=0; }
}

// ---------------- CSR build on dst ----------------
__global__ void k_hist(const int* __restrict__ dst){
    int e = blockIdx.x*256 + threadIdx.x;
    if (e < Ee) atomicAdd(&g_deg[dst[e]], 1);
}

__global__ void k_scan1(){
    __shared__ int s[1024];
    int tid = threadIdx.x;
    int i = blockIdx.x*1024 + tid;
    int v = (i<Nn) ? g_deg[i] : 0;
    s[tid] = v; __syncthreads();
    #pragma unroll
    for (int off=1; off<1024; off<<=1){
        int t = (tid>=off) ? s[tid-off] : 0;
        __syncthreads();
        s[tid] += t;
        __syncthreads();
    }
    if (i<Nn) g_offs[i] = s[tid] - v;
    if (tid==1023) g_bsum[blockIdx.x] = s[1023];
}

__global__ void k_scan2(){
    if (threadIdx.x==0){
        int acc = 0;
        for (int b=0;b<NBLK_SCAN;b++){ g_boff[b]=acc; acc+=g_bsum[b]; }
        g_boff[NBLK_SCAN]=acc;
        g_offs[Nn]=acc;
    }
}

__global__ void k_scan3(){
    int i = blockIdx.x*1024 + threadIdx.x;
    if (i<Nn) g_offs[i] += g_boff[blockIdx.x];
}

__global__ void k_fill(const int* __restrict__ dst){
    int e = blockIdx.x*256 + threadIdx.x;
    if (e < Ee){
        int d = dst[e];
        int p = atomicAdd(&g_cnt[d], 1);
        g_csr[g_offs[d]+p] = e;
    }
}

// ---------------- graph boundaries ----------------
__global__ void k_gstart(const int* __restrict__ batch){
    int g = threadIdx.x;
    if (g > Gg) return;
    int lo = 0, hi = Nn;
    while (lo < hi){
        int mid = (lo+hi) >> 1;
        if (batch[mid] < g) lo = mid+1; else hi = mid;
    }
    g_gstart[g] = lo;
}

// ---------------- aggregation (half2-vectorized; thread = (centroid, h2)) ----------------
__global__ void k_agg(const __half* __restrict__ xin, const float* __restrict__ em,
                      const int* __restrict__ src, const float* __restrict__ epsp,
                      int l, __half* __restrict__ hout){
    const int n = blockIdx.x;
    const int c = threadIdx.x >> 6, i = threadIdx.x & 63;   // 256 threads
    const float ep = 1.0f + epsp[l];
    const int beg = g_offs[n], end = g_offs[n+1];
    const __half2* xc = (const __half2*)xin + (size_t)c*Nn*64;
    const __half2* ee2 = (const __half2*)g_eeh;
    float2 a;
    {
        float2 v = __half22float2(xc[(size_t)n*64 + i]);
        a.x = ep*v.x; a.y = ep*v.y;
    }
    for (int k = beg; k < end; k++){
        int e = g_csr[k];
        int s = src[e];
        float2 ev = __half22float2(ee2[(size_t)e*64 + i]);
        float m = em[(size_t)c*Ee + e];
        float2 xv = __half22float2(xc[(size_t)s*64 + i]);
        a.x += gelu_f(xv.x + ev.x) * m;
        a.y += gelu_f(xv.y + ev.y) * m;
    }
    ((__half2*)hout)[(size_t)c*Nn*64 + (size_t)n*64 + i] = __floats2half2_rn(a.x, a.y);
}

// ---------------- masked mean pool (fp16 y) ----------------
__global__ void k_pool(const __half* __restrict__ y, const float* __restrict__ nm,
                       float* __restrict__ out){
    __shared__ float snum[512];
    __shared__ float sden[4];
    int f = threadIdx.x & 127;
    int slice = threadIdx.x >> 7;
    int g = blockIdx.x, c = blockIdx.y;
    int beg = g_gstart[g], end = g_gstart[g+1];
    float num = 0.f, den = 0.f;
    for (int n=beg+slice; n<end; n+=4){
        float m = nm[c*Nn+n];
        num += __half2float(y[(size_t)(c*Nn+n)*Hd+f])*m;
        den += m;
    }
    snum[threadIdx.x] = num;
    if (f==0) sden[slice] = den;
    __syncthreads();
    if (slice==0){
        float tot = snum[f] + snum[128+f] + snum[256+f] + snum[384+f];
        float d = sden[0]+sden[1]+sden[2]+sden[3] + 1e-7f;
        out[(g*Cc+c)*Hd+f] = tot / d;
    }
}

// ---------------- launch ----------------
extern "C" void kernel_launch(void* const* d_in, const int* in_sizes, int n_in,
                              void* d_out, int out_size){
    const float* x    = (const float*)d_in[0];
    const int*  batch = (const int*)d_in[1];
    const int*  eidx  = (const int*)d_in[2];
    const float* ea   = (const float*)d_in[3];
    const float* nm   = (const float*)d_in[4];
    const float* em   = (const float*)d_in[5];
    const float* Wbe  = (const float*)d_in[6];
    const float* bbe  = (const float*)d_in[7];
    const float* eps  = (const float*)d_in[8];
    const float* W1   = (const float*)d_in[9];
    const float* b1   = (const float*)d_in[10];
    const float* W2   = (const float*)d_in[11];
    const float* b2   = (const float*)d_in[12];
    const float* Wm1  = (const float*)d_in[13];
    const float* bm1  = (const float*)d_in[14];
    const float* Wm2  = (const float*)d_in[15];
    const float* bm2  = (const float*)d_in[16];
    float* out = (float*)d_out;

    const int* src = eidx;
    const int* dst = eidx + Ee;

    __half *xh, *bufA, *bufB, *wsp;
    cudaGetSymbolAddress((void**)&xh,   g_xh);
    cudaGetSymbolAddress((void**)&bufA, g_bufA);
    cudaGetSymbolAddress((void**)&bufB, g_bufB);
    cudaGetSymbolAddress((void**)&wsp,  g_wsp);
    cudaFuncSetAttribute(k_mlp_mma, cudaFuncAttributeMaxDynamicSharedMemorySize, SMEM_MMA);

    // prep
    k_prepw_all<<<dim3(64, 6), 256>>>(W1, W2, Wm1, Wm2, wsp);
    k_x2h<<<(NROWS*Hd/4 + 255)/256, 256>>>(x, xh);
    k_zero_counts<<<(Nn+255)/256, 256>>>();
    k_bond_mma<<<(Ee+255)/256, 512>>>(ea, Wbe, bbe);
    k_hist<<<(Ee+255)/256, 256>>>(dst);
    k_scan1<<<NBLK_SCAN, 1024>>>();
    k_scan2<<<1, 32>>>();
    k_scan3<<<NBLK_SCAN, 1024>>>();
    k_fill<<<(Ee+255)/256, 256>>>(dst);
    k_gstart<<<1, 128>>>(batch);

    const int mlp_grid = (NROWS + 255)/256;

    // layer 0
    k_agg<<<Nn, 256>>>(xh, em, src, eps, 0, bufA);
    k_mlp_mma<<<mlp_grid, 512, SMEM_MMA>>>(bufA, bufB,
        wsp + 0*16384, wsp + 1*16384, wsp + 2*16384, wsp + 3*16384, b1, b2, NROWS, 1);
    // layer 1
    k_agg<<<Nn, 256>>>(bufB, em, src, eps, 1, bufA);
    k_mlp_mma<<<mlp_grid, 512, SMEM_MMA>>>(bufA, bufB,
        wsp + 4*16384, wsp + 5*16384, wsp + 6*16384, wsp + 7*16384, b1 + Hd, b2 + Hd, NROWS, 1);
    // final MLP (no outer gelu)
    k_mlp_mma<<<mlp_grid, 512, SMEM_MMA>>>(bufB, bufA,
        wsp + 8*16384, wsp + 9*16384, wsp + 10*16384, wsp + 11*16384, bm1, bm2, NROWS, 0);
    // pool
    k_pool<<<dim3(Gg, Cc), 512>>>(bufA, nm, out);
}

// round 13
// speedup vs baseline: 2.0570x; 1.0338x over previous
#include <cuda_runtime.h>
#include <cuda_fp16.h>
#include <cstdint>
#include <cstring>
#include <math.h>

#define Nn 50000
#define Ee 200000
#define Hd 128
#define Cc 4
#define Gg 64
#define EDd 16
#define NROWS (Cc*Nn)   // 200000
#define NBLK_SCAN ((Nn + 1023)/1024)   // 49
#define MLP_GRID 152

// ---------------- scratch (device globals; no allocation allowed) ----------------
__device__ __align__(128) __half g_eeh[Ee*Hd];
__device__ __align__(128) __half g_xh[NROWS*Hd];
__device__ __align__(128) __half g_bufA[NROWS*Hd];
__device__ __align__(128) __half g_bufB[NROWS*Hd];
__device__ int g_deg[Nn];
__device__ int g_offs[Nn+1];
__device__ int g_cnt[Nn];
__device__ int g_csr[Ee];
__device__ int g_gstart[Gg+1];
__device__ int g_bsum[NBLK_SCAN];
__device__ int g_boff[NBLK_SCAN+1];
// pre-split weights: 6 matrices x {hi,lo} x 16384 fp16, row-major [k][n]
__device__ __align__(128) __half g_wsp[6*2*16384];

__device__ __forceinline__ float gelu_f(float v){
    return 0.5f*v*(1.0f+erff(v*0.7071067811865475f));
}

__device__ __forceinline__ uint32_t smem_u32(const void* p){
    uint32_t a;
    asm("{ .reg .u64 t; cvta.to.shared.u64 t, %1; cvt.u32.u64 %0, t; }" : "=r"(a) : "l"(p));
    return a;
}
__device__ __forceinline__ void ldsm_x4(uint32_t& r0, uint32_t& r1, uint32_t& r2, uint32_t& r3, uint32_t addr){
    asm volatile("ldmatrix.sync.aligned.m8n8.x4.shared.b16 {%0,%1,%2,%3}, [%4];"
        : "=r"(r0), "=r"(r1), "=r"(r2), "=r"(r3) : "r"(addr));
}
__device__ __forceinline__ void ldsm_x4t(uint32_t* r, uint32_t addr){
    asm volatile("ldmatrix.sync.aligned.m8n8.x4.trans.shared.b16 {%0,%1,%2,%3}, [%4];"
        : "=r"(r[0]), "=r"(r[1]), "=r"(r[2]), "=r"(r[3]) : "r"(addr));
}
__device__ __forceinline__ void mma_fp16(float* c, const uint32_t* a, uint32_t b0, uint32_t b1){
    asm volatile("mma.sync.aligned.m16n8k16.row.col.f32.f16.f16.f32 "
        "{%0,%1,%2,%3},{%4,%5,%6,%7},{%8,%9},{%0,%1,%2,%3};"
        : "+f"(c[0]), "+f"(c[1]), "+f"(c[2]), "+f"(c[3])
        : "r"(a[0]), "r"(a[1]), "r"(a[2]), "r"(a[3]), "r"(b0), "r"(b1));
}
__device__ __forceinline__ uint32_t pack_h2(float a, float b){
    __half2 t = __floats2half2_rn(a, b);
    uint32_t u; memcpy(&u, &t, 4); return u;
}
#define BARW(id) asm volatile("bar.sync %0, 128;" :: "r"(id) : "memory")

// ---------------- weight prep ----------------
__global__ void k_prepw_all(const float* __restrict__ W1, const float* __restrict__ W2,
                            const float* __restrict__ Wm1, const float* __restrict__ Wm2,
                            __half* __restrict__ outw){
    int mat = blockIdx.y;
    const float* src;
    switch (mat){
        case 0: src = W1;          break;
        case 1: src = W2;          break;
        case 2: src = W1 + 16384;  break;
        case 3: src = W2 + 16384;  break;
        case 4: src = Wm1;         break;
        default: src = Wm2;        break;
    }
    int idx = blockIdx.x*256 + threadIdx.x;
    if (idx >= 16384) return;
    float w = src[idx];
    __half h = __float2half_rn(w);
    __half l = __float2half_rn(w - __half2float(h));
    outw[(mat*2+0)*16384 + idx] = h;
    outw[(mat*2+1)*16384 + idx] = l;
}

// ---------------- x fp32 -> fp16 ----------------
__global__ void k_x2h(const float* __restrict__ x, __half* __restrict__ xh){
    int i = blockIdx.x*256 + threadIdx.x;
    if (i < NROWS*Hd/4){
        float4 v = ((const float4*)x)[i];
        uint2 o; o.x = pack_h2(v.x, v.y); o.y = pack_h2(v.z, v.w);
        ((uint2*)xh)[i] = o;
    }
}

// ---------------- bond encoder via mma ----------------
#define LDB_A 24
__global__ void __launch_bounds__(512, 2)
k_bond_mma(const float* __restrict__ ea, const float* __restrict__ Wbe,
           const float* __restrict__ bbe){
    __shared__ __half sA[256*LDB_A];
    __shared__ __half sWh[16*136];
    __shared__ __half sWl[16*136];
    const int tid = threadIdx.x;
    const int base = blockIdx.x*256;

    #pragma unroll
    for (int i = tid; i < 2048; i += 512){
        int k = i >> 7, n = i & 127;
        float w = Wbe[i];
        __half h = __float2half_rn(w);
        sWh[k*136 + n] = h;
        sWl[k*136 + n] = __float2half_rn(w - __half2float(h));
    }
    #pragma unroll
    for (int i = tid; i < 1024; i += 512){
        int row = i >> 2, c4 = (i & 3)*4;
        float4 v = make_float4(0.f,0.f,0.f,0.f);
        if (base + row < Ee) v = *(const float4*)&ea[(size_t)(base+row)*EDd + c4];
        uint2 o; o.x = pack_h2(v.x, v.y); o.y = pack_h2(v.z, v.w);
        *(uint2*)&sA[row*LDB_A + c4] = o;
    }
    __syncthreads();

    const uint32_t sbA = smem_u32(sA), sbWh = smem_u32(sWh), sbWl = smem_u32(sWl);
    const int w = tid >> 5, lane = tid & 31;
    const int wm = w & 7, wn = w >> 3;      // 8 m-groups x 2 n-halves (256 rows x 128 cols)
    const int m0 = wm*32;
    const int grp = lane >> 2, quad = lane & 3;

    uint32_t a0[4], a1[4];
    {
        uint32_t aaddr = sbA + 2u*((uint32_t)((m0 + (lane&15))*LDB_A + (lane>>4)*8));
        ldsm_x4(a0[0], a0[1], a0[2], a0[3], aaddr);
        ldsm_x4(a1[0], a1[1], a1[2], a1[3], aaddr + 16*LDB_A*2);
    }
    float acc[2][8][4];
    #pragma unroll
    for (int mt = 0; mt < 2; mt++)
        #pragma unroll
        for (int nt = 0; nt < 8; nt++){ acc[mt][nt][0]=0.f; acc[mt][nt][1]=0.f; acc[mt][nt][2]=0.f; acc[mt][nt][3]=0.f; }

    {
        uint32_t bh_base = sbWh + 2u*((uint32_t)((lane&15)*136 + wn*64 + (lane>>4)*8));
        uint32_t bl_base = sbWl + 2u*((uint32_t)((lane&15)*136 + wn*64 + (lane>>4)*8));
        #pragma unroll
        for (int ntp = 0; ntp < 4; ntp++){
            uint32_t bh[4], bl[4];
            ldsm_x4t(bh, bh_base + ntp*32);
            ldsm_x4t(bl, bl_base + ntp*32);
            mma_fp16(acc[0][2*ntp],   a0, bh[0], bh[1]);
            mma_fp16(acc[0][2*ntp],   a0, bl[0], bl[1]);
            mma_fp16(acc[1][2*ntp],   a1, bh[0], bh[1]);
            mma_fp16(acc[1][2*ntp],   a1, bl[0], bl[1]);
            mma_fp16(acc[0][2*ntp+1], a0, bh[2], bh[3]);
            mma_fp16(acc[0][2*ntp+1], a0, bl[2], bl[3]);
            mma_fp16(acc[1][2*ntp+1], a1, bh[2], bh[3]);
            mma_fp16(acc[1][2*ntp+1], a1, bl[2], bl[3]);
        }
    }
    #pragma unroll
    for (int mt = 0; mt < 2; mt++){
        int r0 = m0 + mt*16 + grp, r1 = r0 + 8;
        bool v0 = (base + r0) < Ee, v1 = (base + r1) < Ee;
        #pragma unroll
        for (int nt = 0; nt < 8; nt++){
            int n = wn*64 + nt*8 + quad*2;
            float b0 = bbe[n], b1 = bbe[n+1];
            if (v0) *(uint32_t*)&g_eeh[(size_t)(base+r0)*Hd + n] = pack_h2(acc[mt][nt][0]+b0, acc[mt][nt][1]+b1);
            if (v1) *(uint32_t*)&g_eeh[(size_t)(base+r1)*Hd + n] = pack_h2(acc[mt][nt][2]+b0, acc[mt][nt][3]+b1);
        }
    }
}

// ---------------- persistent mma MLP: 128-row tiles, 512 thr (16 warps = 4m x 4n of 32x32) ----------------
#define LDA 136
#define SM_A0  0
#define SM_A1  (128*LDA)
#define SM_WAH (256*LDA)
#define SM_WAL (256*LDA + 128*LDA)
#define SM_WBH (256*LDA + 2*128*LDA)
#define SM_WBL (256*LDA + 3*128*LDA)
#define SMEM_MMA ((256*LDA + 4*128*LDA)*2)   // 208896 bytes

__device__ __forceinline__ void cp_async16(uint32_t dst, const void* src, int nbytes){
    asm volatile("cp.async.ca.shared.global [%0], [%1], 16, %2;"
        :: "r"(dst), "l"(src), "r"(nbytes));
}
#define CP_COMMIT() asm volatile("cp.async.commit_group;" ::: "memory")
#define CP_WAIT0()  asm volatile("cp.async.wait_group 0;" ::: "memory")

__device__ __forceinline__ void load_A_async(uint32_t sbuf, const __half* __restrict__ in,
                                             int base, int rows, int tid){
    #pragma unroll
    for (int i = tid; i < 2048; i += 512){
        int row = i >> 4, c8 = (i & 15)*8;
        uint32_t dst = sbuf + 2u*((uint32_t)(row*LDA + c8));
        int r = base + row;
        int nb = (r < rows) ? 16 : 0;
        if (r >= rows) r = rows - 1;              // clamp: address always in-bounds
        const __half* src = in + (size_t)r*Hd + c8;
        cp_async16(dst, src, nb);
    }
}

// warp tile: 32 rows x 32 cols; acc[mt][nt][4], mt in {0,1}, nt in 0..3
__device__ __forceinline__ void gemm_2t(uint32_t sb, int a_off, int w_h, int w_l,
                                        float acc[2][4][4], int m0, int wn, int lane){
    uint32_t aaddr  = sb + 2u*((uint32_t)(a_off + (m0 + (lane&15))*LDA + (lane>>4)*8));
    uint32_t baddrh = sb + 2u*((uint32_t)(w_h + (lane&15)*LDA + wn*32 + (lane>>4)*8));
    uint32_t baddrl = sb + 2u*((uint32_t)(w_l + (lane&15)*LDA + wn*32 + (lane>>4)*8));
    #pragma unroll
    for (int kb = 0; kb < 8; kb++){
        uint32_t a0[4], a1[4];
        ldsm_x4(a0[0], a0[1], a0[2], a0[3], aaddr + kb*32);
        ldsm_x4(a1[0], a1[1], a1[2], a1[3], aaddr + 16*LDA*2 + kb*32);
        uint32_t bstep = (uint32_t)kb*(16*LDA*2);
        #pragma unroll
        for (int ntp = 0; ntp < 2; ntp++){
            uint32_t bh[4], bl[4];
            ldsm_x4t(bh, baddrh + bstep + ntp*32);
            ldsm_x4t(bl, baddrl + bstep + ntp*32);
            mma_fp16(acc[0][2*ntp],   a0, bh[0], bh[1]);
            mma_fp16(acc[0][2*ntp],   a0, bl[0], bl[1]);
            mma_fp16(acc[1][2*ntp],   a1, bh[0], bh[1]);
            mma_fp16(acc[1][2*ntp],   a1, bl[0], bl[1]);
            mma_fp16(acc[0][2*ntp+1], a0, bh[2], bh[3]);
            mma_fp16(acc[0][2*ntp+1], a0, bl[2], bl[3]);
            mma_fp16(acc[1][2*ntp+1], a1, bh[2], bh[3]);
            mma_fp16(acc[1][2*ntp+1], a1, bl[2], bl[3]);
        }
    }
}

__global__ void __launch_bounds__(512, 1)
k_mlp_mma(const __half* __restrict__ in, __half* __restrict__ out,
          const __half* __restrict__ wa_hi, const __half* __restrict__ wa_lo,
          const __half* __restrict__ wb_hi, const __half* __restrict__ wb_lo,
          const float* __restrict__ ba, const float* __restrict__ bb,
          int rows, int outer_gelu){
    extern __shared__ __half sm[];
    const uint32_t sb = smem_u32(sm);
    const int tid = threadIdx.x;
    const int ntiles = (rows + 127) >> 7;

    {   // weights gmem -> padded smem, ONCE per CTA
        const uint4* s0 = (const uint4*)wa_hi; const uint4* s1 = (const uint4*)wa_lo;
        const uint4* s2 = (const uint4*)wb_hi; const uint4* s3 = (const uint4*)wb_lo;
        #pragma unroll
        for (int i = tid; i < 2048; i += 512){
            int row = i >> 4, c8 = (i & 15)*8;
            int d = row*LDA + c8;
            *(uint4*)&sm[SM_WAH + d] = s0[i];
            *(uint4*)&sm[SM_WAL + d] = s1[i];
            *(uint4*)&sm[SM_WBH + d] = s2[i];
            *(uint4*)&sm[SM_WBL + d] = s3[i];
        }
    }
    int tile = blockIdx.x;
    if (tile < ntiles) load_A_async(sb, in, tile << 7, rows, tid);
    CP_COMMIT();

    const int w = tid >> 5, lane = tid & 31;
    const int wm = w & 3, wn = w >> 2;   // 4 m-groups (32 rows) x 4 n-groups (32 cols)
    const int m0 = wm*32;
    const int grp = lane >> 2, quad = lane & 3;
    const int pair_bar = 1 + wm;         // 4 warps share A rows m0..m0+31 (count=128)
    int buf = 0;

    for (; tile < ntiles; tile += MLP_GRID){
        CP_WAIT0();
        __syncthreads();     // A(buf) ready; prior tile's reads complete
        int next = tile + MLP_GRID;
        if (next < ntiles) load_A_async(sb + (buf ? 0u : 2u*SM_A1), in, next << 7, rows, tid);
        CP_COMMIT();

        const int a_off = buf ? SM_A1 : SM_A0;
        const int base = tile << 7;
        float acc[2][4][4];

        // ---- GEMM1 ----
        #pragma unroll
        for (int mt = 0; mt < 2; mt++)
            #pragma unroll
            for (int nt = 0; nt < 4; nt++){ acc[mt][nt][0]=0.f; acc[mt][nt][1]=0.f; acc[mt][nt][2]=0.f; acc[mt][nt][3]=0.f; }
        gemm_2t(sb, a_off, SM_WAH, SM_WAL, acc, m0, wn, lane);
        BARW(pair_bar);      // row-group done reading A before overwrite

        // epilogue 1: +bias, gelu, back into A(buf) (each warp writes its 32x32 block)
        #pragma unroll
        for (int mt = 0; mt < 2; mt++){
            int r0 = m0 + mt*16 + grp, r1 = r0 + 8;
            #pragma unroll
            for (int nt = 0; nt < 4; nt++){
                int n = wn*32 + nt*8 + quad*2;
                float b0 = ba[n], b1 = ba[n+1];
                float v00 = gelu_f(acc[mt][nt][0] + b0), v01 = gelu_f(acc[mt][nt][1] + b1);
                float v10 = gelu_f(acc[mt][nt][2] + b0), v11 = gelu_f(acc[mt][nt][3] + b1);
                *(uint32_t*)&sm[a_off + r0*LDA + n] = pack_h2(v00, v01);
                *(uint32_t*)&sm[a_off + r1*LDA + n] = pack_h2(v10, v11);
            }
        }
        BARW(pair_bar);      // row-group writes visible before GEMM2 reads

        // ---- GEMM2 ----
        #pragma unroll
        for (int mt = 0; mt < 2; mt++)
            #pragma unroll
            for (int nt = 0; nt < 4; nt++){ acc[mt][nt][0]=0.f; acc[mt][nt][1]=0.f; acc[mt][nt][2]=0.f; acc[mt][nt][3]=0.f; }
        gemm_2t(sb, a_off, SM_WBH, SM_WBL, acc, m0, wn, lane);

        // epilogue 2: +bias, optional gelu, store fp16
        #pragma unroll
        for (int mt = 0; mt < 2; mt++){
            int r0 = m0 + mt*16 + grp, r1 = r0 + 8;
            bool v0 = (base + r0) < rows, v1 = (base + r1) < rows;
            #pragma unroll
            for (int nt = 0; nt < 4; nt++){
                int n = wn*32 + nt*8 + quad*2;
                float b0 = bb[n], b1 = bb[n+1];
                float o00 = acc[mt][nt][0] + b0, o01 = acc[mt][nt][1] + b1;
                float o10 = acc[mt][nt][2] + b0, o11 = acc[mt][nt][3] + b1;
                if (outer_gelu){ o00=gelu_f(o00); o01=gelu_f(o01); o10=gelu_f(o10); o11=gelu_f(o11); }
                if (v0) *(uint32_t*)&out[(size_t)(base+r0)*Hd + n] = pack_h2(o00, o01);
                if (v1) *(uint32_t*)&out[(size_t)(base+r1)*Hd + n] = pack_h2(o10, o11);
            }
        }
        buf ^= 1;
    }
}

// ---------------- zero counters ----------------
__global__ void k_zero_counts(){
    int i = blockIdx.x*256 + threadIdx.x;
    if (i < Nn){ g_deg[i]=0; g_cnt[i]=0; }
}

// ---------------- CSR build on dst ----------------
__global__ void k_hist(const int* __restrict__ dst){
    int e = blockIdx.x*256 + threadIdx.x;
    if (e < Ee) atomicAdd(&g_deg[dst[e]], 1);
}

__global__ void k_scan1(){
    __shared__ int s[1024];
    int tid = threadIdx.x;
    int i = blockIdx.x*1024 + tid;
    int v = (i<Nn) ? g_deg[i] : 0;
    s[tid] = v; __syncthreads();
    #pragma unroll
    for (int off=1; off<1024; off<<=1){
        int t = (tid>=off) ? s[tid-off] : 0;
        __syncthreads();
        s[tid] += t;
        __syncthreads();
    }
    if (i<Nn) g_offs[i] = s[tid] - v;
    if (tid==1023) g_bsum[blockIdx.x] = s[1023];
}

__global__ void k_scan2(){
    if (threadIdx.x==0){
        int acc = 0;
        for (int b=0;b<NBLK_SCAN;b++){ g_boff[b]=acc; acc+=g_bsum[b]; }
        g_boff[NBLK_SCAN]=acc;
        g_offs[Nn]=acc;
    }
}

__global__ void k_scan3(){
    int i = blockIdx.x*1024 + threadIdx.x;
    if (i<Nn) g_offs[i] += g_boff[blockIdx.x];
}

__global__ void k_fill(const int* __restrict__ dst){
    int e = blockIdx.x*256 + threadIdx.x;
    if (e < Ee){
        int d = dst[e];
        int p = atomicAdd(&g_cnt[d], 1);
        g_csr[g_offs[d]+p] = e;
    }
}

// ---------------- graph boundaries ----------------
__global__ void k_gstart(const int* __restrict__ batch){
    int g = threadIdx.x;
    if (g > Gg) return;
    int lo = 0, hi = Nn;
    while (lo < hi){
        int mid = (lo+hi) >> 1;
        if (batch[mid] < g) lo = mid+1; else hi = mid;
    }
    g_gstart[g] = lo;
}

// ---------------- aggregation (half2-vectorized, index-prefetched) ----------------
__global__ void k_agg(const __half* __restrict__ xin, const float* __restrict__ em,
                      const int* __restrict__ src, const float* __restrict__ epsp,
                      int l, __half* __restrict__ hout){
    const int n = blockIdx.x;
    const int c = threadIdx.x >> 6, i = threadIdx.x & 63;   // 256 threads
    const float ep = 1.0f + epsp[l];
    const int beg = g_offs[n], end = g_offs[n+1];
    const __half2* xc = (const __half2*)xin + (size_t)c*Nn*64;
    const __half2* ee2 = (const __half2*)g_eeh;
    float2 a;
    {
        float2 v = __half22float2(xc[(size_t)n*64 + i]);
        a.x = ep*v.x; a.y = ep*v.y;
    }
    int e = 0, s = 0;
    if (beg < end){ e = g_csr[beg]; s = src[e]; }
    for (int k = beg; k < end; k++){
        int e_n = 0, s_n = 0;
        if (k + 1 < end){ e_n = g_csr[k+1]; s_n = src[e_n]; }
        float2 ev = __half22float2(ee2[(size_t)e*64 + i]);
        float m = em[(size_t)c*Ee + e];
        float2 xv = __half22float2(xc[(size_t)s*64 + i]);
        a.x += gelu_f(xv.x + ev.x) * m;
        a.y += gelu_f(xv.y + ev.y) * m;
        e = e_n; s = s_n;
    }
    ((__half2*)hout)[(size_t)c*Nn*64 + (size_t)n*64 + i] = __floats2half2_rn(a.x, a.y);
}

// ---------------- masked mean pool ----------------
__global__ void k_pool(const __half* __restrict__ y, const float* __restrict__ nm,
                       float* __restrict__ out){
    __shared__ float snum[512];
    __shared__ float sden[4];
    int f = threadIdx.x & 127;
    int slice = threadIdx.x >> 7;
    int g = blockIdx.x, c = blockIdx.y;
    int beg = g_gstart[g], end = g_gstart[g+1];
    float num = 0.f, den = 0.f;
    for (int n=beg+slice; n<end; n+=4){
        float m = nm[c*Nn+n];
        num += __half2float(y[(size_t)(c*Nn+n)*Hd+f])*m;
        den += m;
    }
    snum[threadIdx.x] = num;
    if (f==0) sden[slice] = den;
    __syncthreads();
    if (slice==0){
        float tot = snum[f] + snum[128+f] + snum[256+f] + snum[384+f];
        float d = sden[0]+sden[1]+sden[2]+sden[3] + 1e-7f;
        out[(g*Cc+c)*Hd+f] = tot / d;
    }
}

// ---------------- launch ----------------
extern "C" void kernel_launch(void* const* d_in, const int* in_sizes, int n_in,
                              void* d_out, int out_size){
    const float* x    = (const float*)d_in[0];
    const int*  batch = (const int*)d_in[1];
    const int*  eidx  = (const int*)d_in[2];
    const float* ea   = (const float*)d_in[3];
    const float* nm   = (const float*)d_in[4];
    const float* em   = (const float*)d_in[5];
    const float* Wbe  = (const float*)d_in[6];
    const float* bbe  = (const float*)d_in[7];
    const float* eps  = (const float*)d_in[8];
    const float* W1   = (const float*)d_in[9];
    const float* b1   = (const float*)d_in[10];
    const float* W2   = (const float*)d_in[11];
    const float* b2   = (const float*)d_in[12];
    const float* Wm1  = (const float*)d_in[13];
    const float* bm1  = (const float*)d_in[14];
    const float* Wm2  = (const float*)d_in[15];
    const float* bm2  = (const float*)d_in[16];
    float* out = (float*)d_out;

    const int* src = eidx;
    const int* dst = eidx + Ee;

    __half *xh, *bufA, *bufB, *wsp;
    cudaGetSymbolAddress((void**)&xh,   g_xh);
    cudaGetSymbolAddress((void**)&bufA, g_bufA);
    cudaGetSymbolAddress((void**)&bufB, g_bufB);
    cudaGetSymbolAddress((void**)&wsp,  g_wsp);
    cudaFuncSetAttribute(k_mlp_mma, cudaFuncAttributeMaxDynamicSharedMemorySize, SMEM_MMA);

    // prep
    k_prepw_all<<<dim3(64, 6), 256>>>(W1, W2, Wm1, Wm2, wsp);
    k_x2h<<<(NROWS*Hd/4 + 255)/256, 256>>>(x, xh);
    k_zero_counts<<<(Nn+255)/256, 256>>>();
    k_bond_mma<<<(Ee+255)/256, 512>>>(ea, Wbe, bbe);
    k_hist<<<(Ee+255)/256, 256>>>(dst);
    k_scan1<<<NBLK_SCAN, 1024>>>();
    k_scan2<<<1, 32>>>();
    k_scan3<<<NBLK_SCAN, 1024>>>();
    k_fill<<<(Ee+255)/256, 256>>>(dst);
    k_gstart<<<1, 128>>>(batch);

    // layer 0
    k_agg<<<Nn, 256>>>(xh, em, src, eps, 0, bufA);
    k_mlp_mma<<<MLP_GRID, 512, SMEM_MMA>>>(bufA, bufB,
        wsp + 0*16384, wsp + 1*16384, wsp + 2*16384, wsp + 3*16384, b1, b2, NROWS, 1);
    // layer 1
    k_agg<<<Nn, 256>>>(bufB, em, src, eps, 1, bufA);
    k_mlp_mma<<<MLP_GRID, 512, SMEM_MMA>>>(bufA, bufB,
        wsp + 4*16384, wsp + 5*16384, wsp + 6*16384, wsp + 7*16384, b1 + Hd, b2 + Hd, NROWS, 1);
    // final MLP (no outer gelu)
    k_mlp_mma<<<MLP_GRID, 512, SMEM_MMA>>>(bufB, bufA,
        wsp + 8*16384, wsp + 9*16384, wsp + 10*16384, wsp + 11*16384, bm1, bm2, NROWS, 0);
    // pool
    k_pool<<<dim3(Gg, Cc), 512>>>(bufA, nm, out);
}

// round 14
// speedup vs baseline: 2.2687x; 1.1029x over previous
#include <cuda_runtime.h>
#include <cuda_fp16.h>
#include <cstdint>
#include <cstring>
#include <math.h>

#define Nn 50000
#define Ee 200000
#define Hd 128
#define Cc 4
#define Gg 64
#define EDd 16
#define NROWS (Cc*Nn)   // 200000
#define NBLK_SCAN ((Nn + 1023)/1024)   // 49
#define MLP_GRID 152

// ---------------- scratch (device globals; no allocation allowed) ----------------
__device__ __align__(128) __half g_eeh[Ee*Hd];
__device__ __align__(128) __half g_xh[NROWS*Hd];
__device__ __align__(128) __half g_bufA[NROWS*Hd];
__device__ __align__(128) __half g_bufB[NROWS*Hd];
__device__ int g_deg[Nn];
__device__ int g_offs[Nn+1];
__device__ int g_cnt[Nn];
__device__ int g_csr[Ee];
__device__ int g_gstart[Gg+1];
__device__ int g_bsum[NBLK_SCAN];
__device__ int g_boff[NBLK_SCAN+1];
// fp16 weights: 6 matrices x 16384, row-major [k][n]
__device__ __align__(128) __half g_wsp[6*16384];

__device__ __forceinline__ float gelu_f(float v){
    return 0.5f*v*(1.0f+erff(v*0.7071067811865475f));
}

__device__ __forceinline__ uint32_t smem_u32(const void* p){
    uint32_t a;
    asm("{ .reg .u64 t; cvta.to.shared.u64 t, %1; cvt.u32.u64 %0, t; }" : "=r"(a) : "l"(p));
    return a;
}
__device__ __forceinline__ void ldsm_x4(uint32_t& r0, uint32_t& r1, uint32_t& r2, uint32_t& r3, uint32_t addr){
    asm volatile("ldmatrix.sync.aligned.m8n8.x4.shared.b16 {%0,%1,%2,%3}, [%4];"
        : "=r"(r0), "=r"(r1), "=r"(r2), "=r"(r3) : "r"(addr));
}
__device__ __forceinline__ void ldsm_x4t(uint32_t* r, uint32_t addr){
    asm volatile("ldmatrix.sync.aligned.m8n8.x4.trans.shared.b16 {%0,%1,%2,%3}, [%4];"
        : "=r"(r[0]), "=r"(r[1]), "=r"(r[2]), "=r"(r[3]) : "r"(addr));
}
__device__ __forceinline__ void mma_fp16(float* c, const uint32_t* a, uint32_t b0, uint32_t b1){
    asm volatile("mma.sync.aligned.m16n8k16.row.col.f32.f16.f16.f32 "
        "{%0,%1,%2,%3},{%4,%5,%6,%7},{%8,%9},{%0,%1,%2,%3};"
        : "+f"(c[0]), "+f"(c[1]), "+f"(c[2]), "+f"(c[3])
        : "r"(a[0]), "r"(a[1]), "r"(a[2]), "r"(a[3]), "r"(b0), "r"(b1));
}
__device__ __forceinline__ uint32_t pack_h2(float a, float b){
    __half2 t = __floats2half2_rn(a, b);
    uint32_t u; memcpy(&u, &t, 4); return u;
}
#define BARW(id) asm volatile("bar.sync %0, 128;" :: "r"(id) : "memory")

// ---------------- weight prep: fp32 -> fp16 (all 6 mats) ----------------
__global__ void k_prepw_all(const float* __restrict__ W1, const float* __restrict__ W2,
                            const float* __restrict__ Wm1, const float* __restrict__ Wm2,
                            __half* __restrict__ outw){
    int mat = blockIdx.y;
    const float* src;
    switch (mat){
        case 0: src = W1;          break;
        case 1: src = W2;          break;
        case 2: src = W1 + 16384;  break;
        case 3: src = W2 + 16384;  break;
        case 4: src = Wm1;         break;
        default: src = Wm2;        break;
    }
    int idx = blockIdx.x*256 + threadIdx.x;
    if (idx >= 16384) return;
    outw[mat*16384 + idx] = __float2half_rn(src[idx]);
}

// ---------------- x fp32 -> fp16 ----------------
__global__ void k_x2h(const float* __restrict__ x, __half* __restrict__ xh){
    int i = blockIdx.x*256 + threadIdx.x;
    if (i < NROWS*Hd/4){
        float4 v = ((const float4*)x)[i];
        uint2 o; o.x = pack_h2(v.x, v.y); o.y = pack_h2(v.z, v.w);
        ((uint2*)xh)[i] = o;
    }
}

// ---------------- bond encoder via mma (single fp16 W term) ----------------
#define LDB_A 24
__global__ void __launch_bounds__(512, 2)
k_bond_mma(const float* __restrict__ ea, const float* __restrict__ Wbe,
           const float* __restrict__ bbe){
    __shared__ __half sA[256*LDB_A];
    __shared__ __half sWh[16*136];
    const int tid = threadIdx.x;
    const int base = blockIdx.x*256;

    #pragma unroll
    for (int i = tid; i < 2048; i += 512){
        int k = i >> 7, n = i & 127;
        sWh[k*136 + n] = __float2half_rn(Wbe[i]);
    }
    #pragma unroll
    for (int i = tid; i < 1024; i += 512){
        int row = i >> 2, c4 = (i & 3)*4;
        float4 v = make_float4(0.f,0.f,0.f,0.f);
        if (base + row < Ee) v = *(const float4*)&ea[(size_t)(base+row)*EDd + c4];
        uint2 o; o.x = pack_h2(v.x, v.y); o.y = pack_h2(v.z, v.w);
        *(uint2*)&sA[row*LDB_A + c4] = o;
    }
    __syncthreads();

    const uint32_t sbA = smem_u32(sA), sbWh = smem_u32(sWh);
    const int w = tid >> 5, lane = tid & 31;
    const int wm = w & 7, wn = w >> 3;
    const int m0 = wm*32;
    const int grp = lane >> 2, quad = lane & 3;

    uint32_t a0[4], a1[4];
    {
        uint32_t aaddr = sbA + 2u*((uint32_t)((m0 + (lane&15))*LDB_A + (lane>>4)*8));
        ldsm_x4(a0[0], a0[1], a0[2], a0[3], aaddr);
        ldsm_x4(a1[0], a1[1], a1[2], a1[3], aaddr + 16*LDB_A*2);
    }
    float acc[2][8][4];
    #pragma unroll
    for (int mt = 0; mt < 2; mt++)
        #pragma unroll
        for (int nt = 0; nt < 8; nt++){ acc[mt][nt][0]=0.f; acc[mt][nt][1]=0.f; acc[mt][nt][2]=0.f; acc[mt][nt][3]=0.f; }

    {
        uint32_t bh_base = sbWh + 2u*((uint32_t)((lane&15)*136 + wn*64 + (lane>>4)*8));
        #pragma unroll
        for (int ntp = 0; ntp < 4; ntp++){
            uint32_t bh[4];
            ldsm_x4t(bh, bh_base + ntp*32);
            mma_fp16(acc[0][2*ntp],   a0, bh[0], bh[1]);
            mma_fp16(acc[1][2*ntp],   a1, bh[0], bh[1]);
            mma_fp16(acc[0][2*ntp+1], a0, bh[2], bh[3]);
            mma_fp16(acc[1][2*ntp+1], a1, bh[2], bh[3]);
        }
    }
    #pragma unroll
    for (int mt = 0; mt < 2; mt++){
        int r0 = m0 + mt*16 + grp, r1 = r0 + 8;
        bool v0 = (base + r0) < Ee, v1 = (base + r1) < Ee;
        #pragma unroll
        for (int nt = 0; nt < 8; nt++){
            int n = wn*64 + nt*8 + quad*2;
            float b0 = bbe[n], b1 = bbe[n+1];
            if (v0) *(uint32_t*)&g_eeh[(size_t)(base+r0)*Hd + n] = pack_h2(acc[mt][nt][0]+b0, acc[mt][nt][1]+b1);
            if (v1) *(uint32_t*)&g_eeh[(size_t)(base+r1)*Hd + n] = pack_h2(acc[mt][nt][2]+b0, acc[mt][nt][3]+b1);
        }
    }
}

// ---------------- persistent mma MLP (single fp16 W term) ----------------
#define LDA 136
#define SM_A0  0
#define SM_A1  (128*LDA)
#define SM_WAH (256*LDA)
#define SM_WBH (256*LDA + 128*LDA)
#define SMEM_MMA ((256*LDA + 2*128*LDA)*2)   // 139264 bytes

__device__ __forceinline__ void cp_async16(uint32_t dst, const void* src, int nbytes){
    asm volatile("cp.async.ca.shared.global [%0], [%1], 16, %2;"
        :: "r"(dst), "l"(src), "r"(nbytes));
}
#define CP_COMMIT() asm volatile("cp.async.commit_group;" ::: "memory")
#define CP_WAIT0()  asm volatile("cp.async.wait_group 0;" ::: "memory")

__device__ __forceinline__ void load_A_async(uint32_t sbuf, const __half* __restrict__ in,
                                             int base, int rows, int tid){
    #pragma unroll
    for (int i = tid; i < 2048; i += 512){
        int row = i >> 4, c8 = (i & 15)*8;
        uint32_t dst = sbuf + 2u*((uint32_t)(row*LDA + c8));
        int r = base + row;
        int nb = (r < rows) ? 16 : 0;
        if (r >= rows) r = rows - 1;              // clamp: address always in-bounds
        const __half* src = in + (size_t)r*Hd + c8;
        cp_async16(dst, src, nb);
    }
}

// warp tile: 32 rows x 32 cols; acc[mt][nt][4]
__device__ __forceinline__ void gemm_1t(uint32_t sb, int a_off, int w_h,
                                        float acc[2][4][4], int m0, int wn, int lane){
    uint32_t aaddr  = sb + 2u*((uint32_t)(a_off + (m0 + (lane&15))*LDA + (lane>>4)*8));
    uint32_t baddrh = sb + 2u*((uint32_t)(w_h + (lane&15)*LDA + wn*32 + (lane>>4)*8));
    #pragma unroll
    for (int kb = 0; kb < 8; kb++){
        uint32_t a0[4], a1[4];
        ldsm_x4(a0[0], a0[1], a0[2], a0[3], aaddr + kb*32);
        ldsm_x4(a1[0], a1[1], a1[2], a1[3], aaddr + 16*LDA*2 + kb*32);
        uint32_t bstep = (uint32_t)kb*(16*LDA*2);
        #pragma unroll
        for (int ntp = 0; ntp < 2; ntp++){
            uint32_t bh[4];
            ldsm_x4t(bh, baddrh + bstep + ntp*32);
            mma_fp16(acc[0][2*ntp],   a0, bh[0], bh[1]);
            mma_fp16(acc[1][2*ntp],   a1, bh[0], bh[1]);
            mma_fp16(acc[0][2*ntp+1], a0, bh[2], bh[3]);
            mma_fp16(acc[1][2*ntp+1], a1, bh[2], bh[3]);
        }
    }
}

__global__ void __launch_bounds__(512, 1)
k_mlp_mma(const __half* __restrict__ in, __half* __restrict__ out,
          const __half* __restrict__ wa, const __half* __restrict__ wb,
          const float* __restrict__ ba, const float* __restrict__ bb,
          int rows, int outer_gelu){
    extern __shared__ __half sm[];
    const uint32_t sb = smem_u32(sm);
    const int tid = threadIdx.x;
    const int ntiles = (rows + 127) >> 7;

    {   // weights gmem -> padded smem, ONCE per CTA
        const uint4* s0 = (const uint4*)wa; const uint4* s1 = (const uint4*)wb;
        #pragma unroll
        for (int i = tid; i < 2048; i += 512){
            int row = i >> 4, c8 = (i & 15)*8;
            int d = row*LDA + c8;
            *(uint4*)&sm[SM_WAH + d] = s0[i];
            *(uint4*)&sm[SM_WBH + d] = s1[i];
        }
    }
    int tile = blockIdx.x;
    if (tile < ntiles) load_A_async(sb, in, tile << 7, rows, tid);
    CP_COMMIT();

    const int w = tid >> 5, lane = tid & 31;
    const int wm = w & 3, wn = w >> 2;   // 4 m-groups (32 rows) x 4 n-groups (32 cols)
    const int m0 = wm*32;
    const int grp = lane >> 2, quad = lane & 3;
    const int pair_bar = 1 + wm;
    int buf = 0;

    for (; tile < ntiles; tile += MLP_GRID){
        CP_WAIT0();
        __syncthreads();
        int next = tile + MLP_GRID;
        if (next < ntiles) load_A_async(sb + (buf ? 0u : 2u*SM_A1), in, next << 7, rows, tid);
        CP_COMMIT();

        const int a_off = buf ? SM_A1 : SM_A0;
        const int base = tile << 7;
        float acc[2][4][4];

        // ---- GEMM1 ----
        #pragma unroll
        for (int mt = 0; mt < 2; mt++)
            #pragma unroll
            for (int nt = 0; nt < 4; nt++){ acc[mt][nt][0]=0.f; acc[mt][nt][1]=0.f; acc[mt][nt][2]=0.f; acc[mt][nt][3]=0.f; }
        gemm_1t(sb, a_off, SM_WAH, acc, m0, wn, lane);
        BARW(pair_bar);

        // epilogue 1: +bias, gelu, back into A(buf)
        #pragma unroll
        for (int mt = 0; mt < 2; mt++){
            int r0 = m0 + mt*16 + grp, r1 = r0 + 8;
            #pragma unroll
            for (int nt = 0; nt < 4; nt++){
                int n = wn*32 + nt*8 + quad*2;
                float b0 = ba[n], b1 = ba[n+1];
                float v00 = gelu_f(acc[mt][nt][0] + b0), v01 = gelu_f(acc[mt][nt][1] + b1);
                float v10 = gelu_f(acc[mt][nt][2] + b0), v11 = gelu_f(acc[mt][nt][3] + b1);
                *(uint32_t*)&sm[a_off + r0*LDA + n] = pack_h2(v00, v01);
                *(uint32_t*)&sm[a_off + r1*LDA + n] = pack_h2(v10, v11);
            }
        }
        BARW(pair_bar);

        // ---- GEMM2 ----
        #pragma unroll
        for (int mt = 0; mt < 2; mt++)
            #pragma unroll
            for (int nt = 0; nt < 4; nt++){ acc[mt][nt][0]=0.f; acc[mt][nt][1]=0.f; acc[mt][nt][2]=0.f; acc[mt][nt][3]=0.f; }
        gemm_1t(sb, a_off, SM_WBH, acc, m0, wn, lane);

        // epilogue 2: +bias, optional gelu, store fp16
        #pragma unroll
        for (int mt = 0; mt < 2; mt++){
            int r0 = m0 + mt*16 + grp, r1 = r0 + 8;
            bool v0 = (base + r0) < rows, v1 = (base + r1) < rows;
            #pragma unroll
            for (int nt = 0; nt < 4; nt++){
                int n = wn*32 + nt*8 + quad*2;
                float b0 = bb[n], b1 = bb[n+1];
                float o00 = acc[mt][nt][0] + b0, o01 = acc[mt][nt][1] + b1;
                float o10 = acc[mt][nt][2] + b0, o11 = acc[mt][nt][3] + b1;
                if (outer_gelu){ o00=gelu_f(o00); o01=gelu_f(o01); o10=gelu_f(o10); o11=gelu_f(o11); }
                if (v0) *(uint32_t*)&out[(size_t)(base+r0)*Hd + n] = pack_h2(o00, o01);
                if (v1) *(uint32_t*)&out[(size_t)(base+r1)*Hd + n] = pack_h2(o10, o11);
            }
        }
        buf ^= 1;
    }
}

// ---------------- zero counters ----------------
__global__ void k_zero_counts(){
    int i = blockIdx.x*256 + threadIdx.x;
    if (i < Nn){ g_deg[i]=0; g_cnt[i]=0; }
}

// ---------------- CSR build on dst ----------------
__global__ void k_hist(const int* __restrict__ dst){
    int e = blockIdx.x*256 + threadIdx.x;
    if (e < Ee) atomicAdd(&g_deg[dst[e]], 1);
}

__global__ void k_scan1(){
    __shared__ int s[1024];
    int tid = threadIdx.x;
    int i = blockIdx.x*1024 + tid;
    int v = (i<Nn) ? g_deg[i] : 0;
    s[tid] = v; __syncthreads();
    #pragma unroll
    for (int off=1; off<1024; off<<=1){
        int t = (tid>=off) ? s[tid-off] : 0;
        __syncthreads();
        s[tid] += t;
        __syncthreads();
    }
    if (i<Nn) g_offs[i] = s[tid] - v;
    if (tid==1023) g_bsum[blockIdx.x] = s[1023];
}

__global__ void k_scan2(){
    if (threadIdx.x==0){
        int acc = 0;
        for (int b=0;b<NBLK_SCAN;b++){ g_boff[b]=acc; acc+=g_bsum[b]; }
        g_boff[NBLK_SCAN]=acc;
        g_offs[Nn]=acc;
    }
}

__global__ void k_scan3(){
    int i = blockIdx.x*1024 + threadIdx.x;
    if (i<Nn) g_offs[i] += g_boff[blockIdx.x];
}

__global__ void k_fill(const int* __restrict__ dst){
    int e = blockIdx.x*256 + threadIdx.x;
    if (e < Ee){
        int d = dst[e];
        int p = atomicAdd(&g_cnt[d], 1);
        g_csr[g_offs[d]+p] = e;
    }
}

// ---------------- graph boundaries ----------------
__global__ void k_gstart(const int* __restrict__ batch){
    int g = threadIdx.x;
    if (g > Gg) return;
    int lo = 0, hi = Nn;
    while (lo < hi){
        int mid = (lo+hi) >> 1;
        if (batch[mid] < g) lo = mid+1; else hi = mid;
    }
    g_gstart[g] = lo;
}

// ---------------- aggregation (half2-vectorized, index-prefetched) ----------------
__global__ void k_agg(const __half* __restrict__ xin, const float* __restrict__ em,
                      const int* __restrict__ src, const float* __restrict__ epsp,
                      int l, __half* __restrict__ hout){
    const int n = blockIdx.x;
    const int c = threadIdx.x >> 6, i = threadIdx.x & 63;   // 256 threads
    const float ep = 1.0f + epsp[l];
    const int beg = g_offs[n], end = g_offs[n+1];
    const __half2* xc = (const __half2*)xin + (size_t)c*Nn*64;
    const __half2* ee2 = (const __half2*)g_eeh;
    float2 a;
    {
        float2 v = __half22float2(xc[(size_t)n*64 + i]);
        a.x = ep*v.x; a.y = ep*v.y;
    }
    int e = 0, s = 0;
    if (beg < end){ e = g_csr[beg]; s = src[e]; }
    for (int k = beg; k < end; k++){
        int e_n = 0, s_n = 0;
        if (k + 1 < end){ e_n = g_csr[k+1]; s_n = src[e_n]; }
        float2 ev = __half22float2(ee2[(size_t)e*64 + i]);
        float m = em[(size_t)c*Ee + e];
        float2 xv = __half22float2(xc[(size_t)s*64 + i]);
        a.x += gelu_f(xv.x + ev.x) * m;
        a.y += gelu_f(xv.y + ev.y) * m;
        e = e_n; s = s_n;
    }
    ((__half2*)hout)[(size_t)c*Nn*64 + (size_t)n*64 + i] = __floats2half2_rn(a.x, a.y);
}

// ---------------- masked mean pool ----------------
__global__ void k_pool(const __half* __restrict__ y, const float* __restrict__ nm,
                       float* __restrict__ out){
    __shared__ float snum[512];
    __shared__ float sden[4];
    int f = threadIdx.x & 127;
    int slice = threadIdx.x >> 7;
    int g = blockIdx.x, c = blockIdx.y;
    int beg = g_gstart[g], end = g_gstart[g+1];
    float num = 0.f, den = 0.f;
    for (int n=beg+slice; n<end; n+=4){
        float m = nm[c*Nn+n];
        num += __half2float(y[(size_t)(c*Nn+n)*Hd+f])*m;
        den += m;
    }
    snum[threadIdx.x] = num;
    if (f==0) sden[slice] = den;
    __syncthreads();
    if (slice==0){
        float tot = snum[f] + snum[128+f] + snum[256+f] + snum[384+f];
        float d = sden[0]+sden[1]+sden[2]+sden[3] + 1e-7f;
        out[(g*Cc+c)*Hd+f] = tot / d;
    }
}

// ---------------- launch ----------------
extern "C" void kernel_launch(void* const* d_in, const int* in_sizes, int n_in,
                              void* d_out, int out_size){
    const float* x    = (const float*)d_in[0];
    const int*  batch = (const int*)d_in[1];
    const int*  eidx  = (const int*)d_in[2];
    const float* ea   = (const float*)d_in[3];
    const float* nm   = (const float*)d_in[4];
    const float* em   = (const float*)d_in[5];
    const float* Wbe  = (const float*)d_in[6];
    const float* bbe  = (const float*)d_in[7];
    const float* eps  = (const float*)d_in[8];
    const float* W1   = (const float*)d_in[9];
    const float* b1   = (const float*)d_in[10];
    const float* W2   = (const float*)d_in[11];
    const float* b2   = (const float*)d_in[12];
    const float* Wm1  = (const float*)d_in[13];
    const float* bm1  = (const float*)d_in[14];
    const float* Wm2  = (const float*)d_in[15];
    const float* bm2  = (const float*)d_in[16];
    float* out = (float*)d_out;

    const int* src = eidx;
    const int* dst = eidx + Ee;

    __half *xh, *bufA, *bufB, *wsp;
    cudaGetSymbolAddress((void**)&xh,   g_xh);
    cudaGetSymbolAddress((void**)&bufA, g_bufA);
    cudaGetSymbolAddress((void**)&bufB, g_bufB);
    cudaGetSymbolAddress((void**)&wsp,  g_wsp);
    cudaFuncSetAttribute(k_mlp_mma, cudaFuncAttributeMaxDynamicSharedMemorySize, SMEM_MMA);

    // prep
    k_prepw_all<<<dim3(64, 6), 256>>>(W1, W2, Wm1, Wm2, wsp);
    k_x2h<<<(NROWS*Hd/4 + 255)/256, 256>>>(x, xh);
    k_zero_counts<<<(Nn+255)/256, 256>>>();
    k_bond_mma<<<(Ee+255)/256, 512>>>(ea, Wbe, bbe);
    k_hist<<<(Ee+255)/256, 256>>>(dst);
    k_scan1<<<NBLK_SCAN, 1024>>>();
    k_scan2<<<1, 32>>>();
    k_scan3<<<NBLK_SCAN, 1024>>>();
    k_fill<<<(Ee+255)/256, 256>>>(dst);
    k_gstart<<<1, 128>>>(batch);

    // layer 0
    k_agg<<<Nn, 256>>>(xh, em, src, eps, 0, bufA);
    k_mlp_mma<<<MLP_GRID, 512, SMEM_MMA>>>(bufA, bufB,
        wsp + 0*16384, wsp + 1*16384, b1, b2, NROWS, 1);
    // layer 1
    k_agg<<<Nn, 256>>>(bufB, em, src, eps, 1, bufA);
    k_mlp_mma<<<MLP_GRID, 512, SMEM_MMA>>>(bufA, bufB,
        wsp + 2*16384, wsp + 3*16384, b1 + Hd, b2 + Hd, NROWS, 1);
    // final MLP (no outer gelu)
    k_mlp_mma<<<MLP_GRID, 512, SMEM_MMA>>>(bufB, bufA,
        wsp + 4*16384, wsp + 5*16384, bm1, bm2, NROWS, 0);
    // pool
    k_pool<<<dim3(Gg, Cc), 512>>>(bufA, nm, out);
}

// round 15
// speedup vs baseline: 2.6590x; 1.1720x over previous
#include <cuda_runtime.h>
#include <cuda_fp16.h>
#include <cstdint>
#include <cstring>
#include <math.h>

#define Nn 50000
#define Ee 200000
#define Hd 128
#define Cc 4
#define Gg 64
#define EDd 16
#define NROWS (Cc*Nn)   // 200000
#define NBLK_SCAN ((Nn + 1023)/1024)   // 49
#define MLP_GRID 152

// ---------------- scratch (device globals; no allocation allowed) ----------------
__device__ __align__(128) __half g_eeh[Ee*Hd];
__device__ __align__(128) __half g_xh[NROWS*Hd];
__device__ __align__(128) __half g_bufA[NROWS*Hd];
__device__ __align__(128) __half g_bufB[NROWS*Hd];
__device__ int g_deg[Nn];
__device__ int g_offs[Nn+1];
__device__ int g_cnt[Nn];
__device__ int g_csr[Ee];
__device__ int g_gstart[Gg+1];
__device__ int g_bsum[NBLK_SCAN];
__device__ int g_boff[NBLK_SCAN+1];
// fp16 weights: 6 matrices x 16384, row-major [k][n]
__device__ __align__(128) __half g_wsp[6*16384];

__device__ __forceinline__ float gelu_f(float v){
    return 0.5f*v*(1.0f+erff(v*0.7071067811865475f));
}

__device__ __forceinline__ uint32_t smem_u32(const void* p){
    uint32_t a;
    asm("{ .reg .u64 t; cvta.to.shared.u64 t, %1; cvt.u32.u64 %0, t; }" : "=r"(a) : "l"(p));
    return a;
}
__device__ __forceinline__ void ldsm_x4(uint32_t& r0, uint32_t& r1, uint32_t& r2, uint32_t& r3, uint32_t addr){
    asm volatile("ldmatrix.sync.aligned.m8n8.x4.shared.b16 {%0,%1,%2,%3}, [%4];"
        : "=r"(r0), "=r"(r1), "=r"(r2), "=r"(r3) : "r"(addr));
}
__device__ __forceinline__ void ldsm_x4t(uint32_t* r, uint32_t addr){
    asm volatile("ldmatrix.sync.aligned.m8n8.x4.trans.shared.b16 {%0,%1,%2,%3}, [%4];"
        : "=r"(r[0]), "=r"(r[1]), "=r"(r[2]), "=r"(r[3]) : "r"(addr));
}
__device__ __forceinline__ void mma_fp16(float* c, const uint32_t* a, uint32_t b0, uint32_t b1){
    asm volatile("mma.sync.aligned.m16n8k16.row.col.f32.f16.f16.f32 "
        "{%0,%1,%2,%3},{%4,%5,%6,%7},{%8,%9},{%0,%1,%2,%3};"
        : "+f"(c[0]), "+f"(c[1]), "+f"(c[2]), "+f"(c[3])
        : "r"(a[0]), "r"(a[1]), "r"(a[2]), "r"(a[3]), "r"(b0), "r"(b1));
}
__device__ __forceinline__ uint32_t pack_h2(float a, float b){
    __half2 t = __floats2half2_rn(a, b);
    uint32_t u; memcpy(&u, &t, 4); return u;
}
#define BARW(id) asm volatile("bar.sync %0, 128;" :: "r"(id) : "memory")

// ---------------- weight prep: fp32 -> fp16 (all 6 mats) ----------------
__global__ void k_prepw_all(const float* __restrict__ W1, const float* __restrict__ W2,
                            const float* __restrict__ Wm1, const float* __restrict__ Wm2,
                            __half* __restrict__ outw){
    int mat = blockIdx.y;
    const float* src;
    switch (mat){
        case 0: src = W1;          break;
        case 1: src = W2;          break;
        case 2: src = W1 + 16384;  break;
        case 3: src = W2 + 16384;  break;
        case 4: src = Wm1;         break;
        default: src = Wm2;        break;
    }
    int idx = blockIdx.x*256 + threadIdx.x;
    if (idx >= 16384) return;
    outw[mat*16384 + idx] = __float2half_rn(src[idx]);
}

// ---------------- x fp32 -> fp16 ----------------
__global__ void k_x2h(const float* __restrict__ x, __half* __restrict__ xh){
    int i = blockIdx.x*256 + threadIdx.x;
    if (i < NROWS*Hd/4){
        float4 v = ((const float4*)x)[i];
        uint2 o; o.x = pack_h2(v.x, v.y); o.y = pack_h2(v.z, v.w);
        ((uint2*)xh)[i] = o;
    }
}

// ---------------- bond encoder via mma (single fp16 W term) ----------------
#define LDB_A 24
__global__ void __launch_bounds__(512, 2)
k_bond_mma(const float* __restrict__ ea, const float* __restrict__ Wbe,
           const float* __restrict__ bbe){
    __shared__ __half sA[256*LDB_A];
    __shared__ __half sWh[16*136];
    const int tid = threadIdx.x;
    const int base = blockIdx.x*256;

    #pragma unroll
    for (int i = tid; i < 2048; i += 512){
        int k = i >> 7, n = i & 127;
        sWh[k*136 + n] = __float2half_rn(Wbe[i]);
    }
    #pragma unroll
    for (int i = tid; i < 1024; i += 512){
        int row = i >> 2, c4 = (i & 3)*4;
        float4 v = make_float4(0.f,0.f,0.f,0.f);
        if (base + row < Ee) v = *(const float4*)&ea[(size_t)(base+row)*EDd + c4];
        uint2 o; o.x = pack_h2(v.x, v.y); o.y = pack_h2(v.z, v.w);
        *(uint2*)&sA[row*LDB_A + c4] = o;
    }
    __syncthreads();

    const uint32_t sbA = smem_u32(sA), sbWh = smem_u32(sWh);
    const int w = tid >> 5, lane = tid & 31;
    const int wm = w & 7, wn = w >> 3;
    const int m0 = wm*32;
    const int grp = lane >> 2, quad = lane & 3;

    uint32_t a0[4], a1[4];
    {
        uint32_t aaddr = sbA + 2u*((uint32_t)((m0 + (lane&15))*LDB_A + (lane>>4)*8));
        ldsm_x4(a0[0], a0[1], a0[2], a0[3], aaddr);
        ldsm_x4(a1[0], a1[1], a1[2], a1[3], aaddr + 16*LDB_A*2);
    }
    float acc[2][8][4];
    #pragma unroll
    for (int mt = 0; mt < 2; mt++)
        #pragma unroll
        for (int nt = 0; nt < 8; nt++){ acc[mt][nt][0]=0.f; acc[mt][nt][1]=0.f; acc[mt][nt][2]=0.f; acc[mt][nt][3]=0.f; }

    {
        uint32_t bh_base = sbWh + 2u*((uint32_t)((lane&15)*136 + wn*64 + (lane>>4)*8));
        #pragma unroll
        for (int ntp = 0; ntp < 4; ntp++){
            uint32_t bh[4];
            ldsm_x4t(bh, bh_base + ntp*32);
            mma_fp16(acc[0][2*ntp],   a0, bh[0], bh[1]);
            mma_fp16(acc[1][2*ntp],   a1, bh[0], bh[1]);
            mma_fp16(acc[0][2*ntp+1], a0, bh[2], bh[3]);
            mma_fp16(acc[1][2*ntp+1], a1, bh[2], bh[3]);
        }
    }
    #pragma unroll
    for (int mt = 0; mt < 2; mt++){
        int r0 = m0 + mt*16 + grp, r1 = r0 + 8;
        bool v0 = (base + r0) < Ee, v1 = (base + r1) < Ee;
        #pragma unroll
        for (int nt = 0; nt < 8; nt++){
            int n = wn*64 + nt*8 + quad*2;
            float b0 = bbe[n], b1 = bbe[n+1];
            if (v0) *(uint32_t*)&g_eeh[(size_t)(base+r0)*Hd + n] = pack_h2(acc[mt][nt][0]+b0, acc[mt][nt][1]+b1);
            if (v1) *(uint32_t*)&g_eeh[(size_t)(base+r1)*Hd + n] = pack_h2(acc[mt][nt][2]+b0, acc[mt][nt][3]+b1);
        }
    }
}

// ---------------- persistent mma MLP (single fp16 W term) ----------------
#define LDA 136
#define SM_A0  0
#define SM_A1  (128*LDA)
#define SM_WAH (256*LDA)
#define SM_WBH (256*LDA + 128*LDA)
#define SMEM_MMA ((256*LDA + 2*128*LDA)*2)   // 139264 bytes

__device__ __forceinline__ void cp_async16(uint32_t dst, const void* src, int nbytes){
    asm volatile("cp.async.ca.shared.global [%0], [%1], 16, %2;"
        :: "r"(dst), "l"(src), "r"(nbytes));
}
#define CP_COMMIT() asm volatile("cp.async.commit_group;" ::: "memory")
#define CP_WAIT0()  asm volatile("cp.async.wait_group 0;" ::: "memory")

__device__ __forceinline__ void load_A_async(uint32_t sbuf, const __half* __restrict__ in,
                                             int base, int rows, int tid){
    #pragma unroll
    for (int i = tid; i < 2048; i += 512){
        int row = i >> 4, c8 = (i & 15)*8;
        uint32_t dst = sbuf + 2u*((uint32_t)(row*LDA + c8));
        int r = base + row;
        int nb = (r < rows) ? 16 : 0;
        if (r >= rows) r = rows - 1;              // clamp: address always in-bounds
        const __half* src = in + (size_t)r*Hd + c8;
        cp_async16(dst, src, nb);
    }
}

// warp tile: 32 rows x 32 cols; acc[mt][nt][4]
__device__ __forceinline__ void gemm_1t(uint32_t sb, int a_off, int w_h,
                                        float acc[2][4][4], int m0, int wn, int lane){
    uint32_t aaddr  = sb + 2u*((uint32_t)(a_off + (m0 + (lane&15))*LDA + (lane>>4)*8));
    uint32_t baddrh = sb + 2u*((uint32_t)(w_h + (lane&15)*LDA + wn*32 + (lane>>4)*8));
    #pragma unroll
    for (int kb = 0; kb < 8; kb++){
        uint32_t a0[4], a1[4];
        ldsm_x4(a0[0], a0[1], a0[2], a0[3], aaddr + kb*32);
        ldsm_x4(a1[0], a1[1], a1[2], a1[3], aaddr + 16*LDA*2 + kb*32);
        uint32_t bstep = (uint32_t)kb*(16*LDA*2);
        #pragma unroll
        for (int ntp = 0; ntp < 2; ntp++){
            uint32_t bh[4];
            ldsm_x4t(bh, baddrh + bstep + ntp*32);
            mma_fp16(acc[0][2*ntp],   a0, bh[0], bh[1]);
            mma_fp16(acc[1][2*ntp],   a1, bh[0], bh[1]);
            mma_fp16(acc[0][2*ntp+1], a0, bh[2], bh[3]);
            mma_fp16(acc[1][2*ntp+1], a1, bh[2], bh[3]);
        }
    }
}

__global__ void __launch_bounds__(512, 1)
k_mlp_mma(const __half* __restrict__ in, __half* __restrict__ out,
          const __half* __restrict__ wa, const __half* __restrict__ wb,
          const float* __restrict__ ba, const float* __restrict__ bb,
          int rows, int outer_gelu){
    extern __shared__ __half sm[];
    const uint32_t sb = smem_u32(sm);
    const int tid = threadIdx.x;
    const int ntiles = (rows + 127) >> 7;

    {   // weights gmem -> padded smem, ONCE per CTA
        const uint4* s0 = (const uint4*)wa; const uint4* s1 = (const uint4*)wb;
        #pragma unroll
        for (int i = tid; i < 2048; i += 512){
            int row = i >> 4, c8 = (i & 15)*8;
            int d = row*LDA + c8;
            *(uint4*)&sm[SM_WAH + d] = s0[i];
            *(uint4*)&sm[SM_WBH + d] = s1[i];
        }
    }
    int tile = blockIdx.x;
    if (tile < ntiles) load_A_async(sb, in, tile << 7, rows, tid);
    CP_COMMIT();

    const int w = tid >> 5, lane = tid & 31;
    const int wm = w & 3, wn = w >> 2;   // 4 m-groups (32 rows) x 4 n-groups (32 cols)
    const int m0 = wm*32;
    const int grp = lane >> 2, quad = lane & 3;
    const int pair_bar = 1 + wm;
    int buf = 0;

    for (; tile < ntiles; tile += MLP_GRID){
        CP_WAIT0();
        __syncthreads();
        int next = tile + MLP_GRID;
        if (next < ntiles) load_A_async(sb + (buf ? 0u : 2u*SM_A1), in, next << 7, rows, tid);
        CP_COMMIT();

        const int a_off = buf ? SM_A1 : SM_A0;
        const int base = tile << 7;
        float acc[2][4][4];

        // ---- GEMM1 ----
        #pragma unroll
        for (int mt = 0; mt < 2; mt++)
            #pragma unroll
            for (int nt = 0; nt < 4; nt++){ acc[mt][nt][0]=0.f; acc[mt][nt][1]=0.f; acc[mt][nt][2]=0.f; acc[mt][nt][3]=0.f; }
        gemm_1t(sb, a_off, SM_WAH, acc, m0, wn, lane);
        BARW(pair_bar);

        // epilogue 1: +bias, gelu, back into A(buf)
        #pragma unroll
        for (int mt = 0; mt < 2; mt++){
            int r0 = m0 + mt*16 + grp, r1 = r0 + 8;
            #pragma unroll
            for (int nt = 0; nt < 4; nt++){
                int n = wn*32 + nt*8 + quad*2;
                float b0 = ba[n], b1 = ba[n+1];
                float v00 = gelu_f(acc[mt][nt][0] + b0), v01 = gelu_f(acc[mt][nt][1] + b1);
                float v10 = gelu_f(acc[mt][nt][2] + b0), v11 = gelu_f(acc[mt][nt][3] + b1);
                *(uint32_t*)&sm[a_off + r0*LDA + n] = pack_h2(v00, v01);
                *(uint32_t*)&sm[a_off + r1*LDA + n] = pack_h2(v10, v11);
            }
        }
        BARW(pair_bar);

        // ---- GEMM2 ----
        #pragma unroll
        for (int mt = 0; mt < 2; mt++)
            #pragma unroll
            for (int nt = 0; nt < 4; nt++){ acc[mt][nt][0]=0.f; acc[mt][nt][1]=0.f; acc[mt][nt][2]=0.f; acc[mt][nt][3]=0.f; }
        gemm_1t(sb, a_off, SM_WBH, acc, m0, wn, lane);

        // epilogue 2: +bias, optional gelu, store fp16
        #pragma unroll
        for (int mt = 0; mt < 2; mt++){
            int r0 = m0 + mt*16 + grp, r1 = r0 + 8;
            bool v0 = (base + r0) < rows, v1 = (base + r1) < rows;
            #pragma unroll
            for (int nt = 0; nt < 4; nt++){
                int n = wn*32 + nt*8 + quad*2;
                float b0 = bb[n], b1 = bb[n+1];
                float o00 = acc[mt][nt][0] + b0, o01 = acc[mt][nt][1] + b1;
                float o10 = acc[mt][nt][2] + b0, o11 = acc[mt][nt][3] + b1;
                if (outer_gelu){ o00=gelu_f(o00); o01=gelu_f(o01); o10=gelu_f(o10); o11=gelu_f(o11); }
                if (v0) *(uint32_t*)&out[(size_t)(base+r0)*Hd + n] = pack_h2(o00, o01);
                if (v1) *(uint32_t*)&out[(size_t)(base+r1)*Hd + n] = pack_h2(o10, o11);
            }
        }
        buf ^= 1;
    }
}

// ---------------- zero counters ----------------
__global__ void k_zero_counts(){
    int i = blockIdx.x*256 + threadIdx.x;
    if (i < Nn){ g_deg[i]=0; g_cnt[i]=0; }
}

// ---------------- CSR build on dst ----------------
__global__ void k_hist(const int* __restrict__ dst){
    int e = blockIdx.x*256 + threadIdx.x;
    if (e < Ee) atomicAdd(&g_deg[dst[e]], 1);
}

__global__ void k_scan1(){
    __shared__ int s[1024];
    int tid = threadIdx.x;
    int i = blockIdx.x*1024 + tid;
    int v = (i<Nn) ? g_deg[i] : 0;
    s[tid] = v; __syncthreads();
    #pragma unroll
    for (int off=1; off<1024; off<<=1){
        int t = (tid>=off) ? s[tid-off] : 0;
        __syncthreads();
        s[tid] += t;
        __syncthreads();
    }
    if (i<Nn) g_offs[i] = s[tid] - v;
    if (tid==1023) g_bsum[blockIdx.x] = s[1023];
}

__global__ void k_scan2(){
    if (threadIdx.x==0){
        int acc = 0;
        for (int b=0;b<NBLK_SCAN;b++){ g_boff[b]=acc; acc+=g_bsum[b]; }
        g_boff[NBLK_SCAN]=acc;
        g_offs[Nn]=acc;
    }
}

__global__ void k_scan3(){
    int i = blockIdx.x*1024 + threadIdx.x;
    if (i<Nn) g_offs[i] += g_boff[blockIdx.x];
}

__global__ void k_fill(const int* __restrict__ dst){
    int e = blockIdx.x*256 + threadIdx.x;
    if (e < Ee){
        int d = dst[e];
        int p = atomicAdd(&g_cnt[d], 1);
        g_csr[g_offs[d]+p] = e;
    }
}

// ---------------- graph boundaries ----------------
__global__ void k_gstart(const int* __restrict__ batch){
    int g = threadIdx.x;
    if (g > Gg) return;
    int lo = 0, hi = Nn;
    while (lo < hi){
        int mid = (lo+hi) >> 1;
        if (batch[mid] < g) lo = mid+1; else hi = mid;
    }
    g_gstart[g] = lo;
}

// ---------------- aggregation: 128 thr (warp = centroid, lane = 4 comps), value-pipelined ----------------
__global__ void k_agg(const __half* __restrict__ xin, const float* __restrict__ em,
                      const int* __restrict__ src, const float* __restrict__ epsp,
                      int l, __half* __restrict__ hout){
    const int n = blockIdx.x;
    const int c = threadIdx.x >> 5;      // warp = centroid
    const int i = threadIdx.x & 31;      // lane covers 4 components (uint2 = 2 half2)
    const float ep = 1.0f + epsp[l];
    const int beg = g_offs[n], end = g_offs[n+1];
    const uint2* xc = (const uint2*)xin + (size_t)c*Nn*32;
    const uint2* ee4 = (const uint2*)g_eeh;

    float4 a;
    {
        uint2 u = xc[(size_t)n*32 + i];
        __half2 h0, h1; memcpy(&h0, &u.x, 4); memcpy(&h1, &u.y, 4);
        float2 v0 = __half22float2(h0), v1 = __half22float2(h1);
        a.x = ep*v0.x; a.y = ep*v0.y; a.z = ep*v1.x; a.w = ep*v1.y;
    }
    if (beg < end){
        // prime pipeline: edge k=beg values
        int e = g_csr[beg];
        int s = src[e];
        uint2 ev = ee4[(size_t)e*32 + i];
        uint2 xv = xc[(size_t)s*32 + i];
        float m = em[(size_t)c*Ee + e];
        for (int k = beg; k < end; k++){
            // prefetch next edge's values while computing current
            uint2 ev_n = ev, xv_n = xv; float m_n = m;
            if (k + 1 < end){
                int e2 = g_csr[k+1];
                int s2 = src[e2];
                ev_n = ee4[(size_t)e2*32 + i];
                xv_n = xc[(size_t)s2*32 + i];
                m_n = em[(size_t)c*Ee + e2];
            }
            __half2 eh0, eh1, xh0, xh1;
            memcpy(&eh0, &ev.x, 4); memcpy(&eh1, &ev.y, 4);
            memcpy(&xh0, &xv.x, 4); memcpy(&xh1, &xv.y, 4);
            float2 e0 = __half22float2(eh0), e1 = __half22float2(eh1);
            float2 x0 = __half22float2(xh0), x1 = __half22float2(xh1);
            a.x += gelu_f(x0.x + e0.x) * m;
            a.y += gelu_f(x0.y + e0.y) * m;
            a.z += gelu_f(x1.x + e1.x) * m;
            a.w += gelu_f(x1.y + e1.y) * m;
            ev = ev_n; xv = xv_n; m = m_n;
        }
    }
    uint2 o; o.x = pack_h2(a.x, a.y); o.y = pack_h2(a.z, a.w);
    ((uint2*)hout)[(size_t)c*Nn*32 + (size_t)n*32 + i] = o;
}

// ---------------- masked mean pool ----------------
__global__ void k_pool(const __half* __restrict__ y, const float* __restrict__ nm,
                       float* __restrict__ out){
    __shared__ float snum[512];
    __shared__ float sden[4];
    int f = threadIdx.x & 127;
    int slice = threadIdx.x >> 7;
    int g = blockIdx.x, c = blockIdx.y;
    int beg = g_gstart[g], end = g_gstart[g+1];
    float num = 0.f, den = 0.f;
    for (int n=beg+slice; n<end; n+=4){
        float m = nm[c*Nn+n];
        num += __half2float(y[(size_t)(c*Nn+n)*Hd+f])*m;
        den += m;
    }
    snum[threadIdx.x] = num;
    if (f==0) sden[slice] = den;
    __syncthreads();
    if (slice==0){
        float tot = snum[f] + snum[128+f] + snum[256+f] + snum[384+f];
        float d = sden[0]+sden[1]+sden[2]+sden[3] + 1e-7f;
        out[(g*Cc+c)*Hd+f] = tot / d;
    }
}

// ---------------- launch ----------------
extern "C" void kernel_launch(void* const* d_in, const int* in_sizes, int n_in,
                              void* d_out, int out_size){
    const float* x    = (const float*)d_in[0];
    const int*  batch = (const int*)d_in[1];
    const int*  eidx  = (const int*)d_in[2];
    const float* ea   = (const float*)d_in[3];
    const float* nm   = (const float*)d_in[4];
    const float* em   = (const float*)d_in[5];
    const float* Wbe  = (const float*)d_in[6];
    const float* bbe  = (const float*)d_in[7];
    const float* eps  = (const float*)d_in[8];
    const float* W1   = (const float*)d_in[9];
    const float* b1   = (const float*)d_in[10];
    const float* W2   = (const float*)d_in[11];
    const float* b2   = (const float*)d_in[12];
    const float* Wm1  = (const float*)d_in[13];
    const float* bm1  = (const float*)d_in[14];
    const float* Wm2  = (const float*)d_in[15];
    const float* bm2  = (const float*)d_in[16];
    float* out = (float*)d_out;

    const int* src = eidx;
    const int* dst = eidx + Ee;

    __half *xh, *bufA, *bufB, *wsp;
    cudaGetSymbolAddress((void**)&xh,   g_xh);
    cudaGetSymbolAddress((void**)&bufA, g_bufA);
    cudaGetSymbolAddress((void**)&bufB, g_bufB);
    cudaGetSymbolAddress((void**)&wsp,  g_wsp);
    cudaFuncSetAttribute(k_mlp_mma, cudaFuncAttributeMaxDynamicSharedMemorySize, SMEM_MMA);

    // prep
    k_prepw_all<<<dim3(64, 6), 256>>>(W1, W2, Wm1, Wm2, wsp);
    k_x2h<<<(NROWS*Hd/4 + 255)/256, 256>>>(x, xh);
    k_zero_counts<<<(Nn+255)/256, 256>>>();
    k_bond_mma<<<(Ee+255)/256, 512>>>(ea, Wbe, bbe);
    k_hist<<<(Ee+255)/256, 256>>>(dst);
    k_scan1<<<NBLK_SCAN, 1024>>>();
    k_scan2<<<1, 32>>>();
    k_scan3<<<NBLK_SCAN, 1024>>>();
    k_fill<<<(Ee+255)/256, 256>>>(dst);
    k_gstart<<<1, 128>>>(batch);

    // layer 0
    k_agg<<<Nn, 128>>>(xh, em, src, eps, 0, bufA);
    k_mlp_mma<<<MLP_GRID, 512, SMEM_MMA>>>(bufA, bufB,
        wsp + 0*16384, wsp + 1*16384, b1, b2, NROWS, 1);
    // layer 1
    k_agg<<<Nn, 128>>>(bufB, em, src, eps, 1, bufA);
    k_mlp_mma<<<MLP_GRID, 512, SMEM_MMA>>>(bufA, bufB,
        wsp + 2*16384, wsp + 3*16384, b1 + Hd, b2 + Hd, NROWS, 1);
    // final MLP (no outer gelu)
    k_mlp_mma<<<MLP_GRID, 512, SMEM_MMA>>>(bufB, bufA,
        wsp + 4*16384, wsp + 5*16384, bm1, bm2, NROWS, 0);
    // pool
    k_pool<<<dim3(Gg, Cc), 512>>>(bufA, nm, out);
}